// round 1
// baseline (speedup 1.0000x reference)
#include <cuda_runtime.h>
#include <cuda_bf16.h>
#include <math.h>
#include <stdint.h>

// ---------------------------------------------------------------------------
// Problem constants
// ---------------------------------------------------------------------------
constexpr int SEQ    = 2048;
constexpr int DIM    = 2048;
constexpr int NH     = 16;
constexpr int QR     = 1536;   // Q_RANK
constexpr int KVR    = 512;    // KV_RANK
constexpr int ROPE_D = 64;
constexpr int NOPE   = 128;
constexpr int VDIM   = 128;
constexpr int QKD    = NOPE + ROPE_D;          // 192
constexpr int KVUP_D = NOPE + VDIM;            // 256
constexpr float EPSF = 1e-6f;

// ---------------------------------------------------------------------------
// Scratch (device globals: allocation-free)
// ---------------------------------------------------------------------------
__device__ __align__(256) float g_cq   [SEQ * QR];            // q down-proj (then normed in place)
__device__ __align__(256) float g_q    [SEQ * NH * QKD];      // q up-proj (rope applied in place)
__device__ __align__(256) float g_kv   [SEQ * (KVR + ROPE_D)];// kv down-proj
__device__ __align__(256) float g_ckv  [SEQ * KVR];           // normed c_kv
__device__ __align__(256) float g_krope[SEQ * ROPE_D];        // roped shared k_rope
__device__ __align__(256) float g_kvup [SEQ * NH * KVUP_D];   // k_nope | v per head
__device__ __align__(256) float g_attn [SEQ * NH * VDIM];     // attention output
__device__ __align__(256) float g_cos  [SEQ * (ROPE_D / 2)];
__device__ __align__(256) float g_sin  [SEQ * (ROPE_D / 2)];

// ---------------------------------------------------------------------------
// GEMM: C[M,N] = A[M,K] * B[N,K]^T   (row-major, both K-contiguous)
// 128x128x8 tiles, 8x8 micro-tile, 256 threads. M % 128 == 0, K % 8 == 0.
// N may be ragged (576 case).
// ---------------------------------------------------------------------------
__global__ void __launch_bounds__(256) gemm_nt_kernel(
    const float* __restrict__ A, const float* __restrict__ B,
    float* __restrict__ C, int M, int N, int K)
{
    constexpr int BM = 128, BN = 128, BK = 8;
    __shared__ float As[BK][BM + 4];   // pad 132 floats: keeps 16B row alignment
    __shared__ float Bs[BK][BN + 4];

    const int tid = threadIdx.x;
    const int tx  = tid & 15;
    const int ty  = tid >> 4;
    const int bm0 = blockIdx.y * BM;
    const int bn0 = blockIdx.x * BN;

    const int lrow = tid >> 1;         // 0..127
    const int lk   = (tid & 1) * 4;    // 0 or 4

    float acc[8][8];
#pragma unroll
    for (int i = 0; i < 8; i++)
#pragma unroll
        for (int j = 0; j < 8; j++) acc[i][j] = 0.f;

    const bool bvalid = (bn0 + lrow) < N;

    for (int k0 = 0; k0 < K; k0 += BK) {
        float4 av = *reinterpret_cast<const float4*>(A + (size_t)(bm0 + lrow) * K + k0 + lk);
        float4 bv = make_float4(0.f, 0.f, 0.f, 0.f);
        if (bvalid)
            bv = *reinterpret_cast<const float4*>(B + (size_t)(bn0 + lrow) * K + k0 + lk);
        As[lk + 0][lrow] = av.x; As[lk + 1][lrow] = av.y;
        As[lk + 2][lrow] = av.z; As[lk + 3][lrow] = av.w;
        Bs[lk + 0][lrow] = bv.x; Bs[lk + 1][lrow] = bv.y;
        Bs[lk + 2][lrow] = bv.z; Bs[lk + 3][lrow] = bv.w;
        __syncthreads();

#pragma unroll
        for (int kk = 0; kk < BK; kk++) {
            float a[8], b[8];
#pragma unroll
            for (int i = 0; i < 8; i++) a[i] = As[kk][ty * 8 + i];
#pragma unroll
            for (int j = 0; j < 8; j++) b[j] = Bs[kk][tx * 8 + j];
#pragma unroll
            for (int i = 0; i < 8; i++)
#pragma unroll
                for (int j = 0; j < 8; j++)
                    acc[i][j] = fmaf(a[i], b[j], acc[i][j]);
        }
        __syncthreads();
    }

#pragma unroll
    for (int i = 0; i < 8; i++) {
        const int row = bm0 + ty * 8 + i;
#pragma unroll
        for (int j = 0; j < 8; j++) {
            const int col = bn0 + tx * 8 + j;
            if (col < N) C[(size_t)row * N + col] = acc[i][j];
        }
    }
}

// ---------------------------------------------------------------------------
// RMSNorm: dst[row, :R] = src[row, :R] * rsqrt(mean(src^2) + eps) * w
// ---------------------------------------------------------------------------
__global__ void __launch_bounds__(256) rmsnorm_kernel(
    const float* __restrict__ src, float* __restrict__ dst,
    const float* __restrict__ w, int R, int sstride, int dstride)
{
    const int row = blockIdx.x;
    const float* s = src + (size_t)row * sstride;
    float* d = dst + (size_t)row * dstride;

    float sum = 0.f;
    for (int i = threadIdx.x; i < R; i += 256) {
        float v = s[i];
        sum = fmaf(v, v, sum);
    }
    __shared__ float red[8];
#pragma unroll
    for (int o = 16; o; o >>= 1) sum += __shfl_down_sync(0xffffffffu, sum, o);
    if ((threadIdx.x & 31) == 0) red[threadIdx.x >> 5] = sum;
    __syncthreads();
    if (threadIdx.x < 8) {
        float v = red[threadIdx.x];
#pragma unroll
        for (int o = 4; o; o >>= 1) v += __shfl_down_sync(0xffu, v, o);
        if (threadIdx.x == 0) red[0] = v;
    }
    __syncthreads();
    const float mean = red[0] / (float)R;
    const float r = rsqrtf(mean + EPSF);
    for (int i = threadIdx.x; i < R; i += 256)
        d[i] = s[i] * r * w[i];
}

// ---------------------------------------------------------------------------
// RoPE tables (cos/sin per (t, pair))
// ---------------------------------------------------------------------------
__global__ void rope_tables_kernel()
{
    const int idx = blockIdx.x * blockDim.x + threadIdx.x;
    if (idx >= SEQ * (ROPE_D / 2)) return;
    const int t = idx / (ROPE_D / 2);
    const int i = idx % (ROPE_D / 2);
    const double freq = pow(500000.0, -(double)i / 32.0);
    const float ang = (float)t * (float)freq;   // mimic fp32 outer() rounding
    g_cos[idx] = cosf(ang);
    g_sin[idx] = sinf(ang);
}

// Apply RoPE to q (last 64 dims of each head), in place
__global__ void rope_q_kernel()
{
    const int idx = blockIdx.x * blockDim.x + threadIdx.x;
    if (idx >= SEQ * NH * (ROPE_D / 2)) return;
    const int i  = idx & 31;
    const int th = idx >> 5;
    const int h  = th % NH;
    const int t  = th / NH;
    const float c = g_cos[t * 32 + i];
    const float s = g_sin[t * 32 + i];
    float* p = g_q + (size_t)t * (NH * QKD) + h * QKD + NOPE + 2 * i;
    const float e = p[0], o = p[1];
    p[0] = e * c - o * s;
    p[1] = o * c + e * s;
}

// Apply RoPE to the shared k_rope (from tail of kv down-proj)
__global__ void rope_k_kernel()
{
    const int idx = blockIdx.x * blockDim.x + threadIdx.x;
    if (idx >= SEQ * (ROPE_D / 2)) return;
    const int i = idx & 31;
    const int t = idx >> 5;
    const float c = g_cos[t * 32 + i];
    const float s = g_sin[t * 32 + i];
    const float* src = g_kv + (size_t)t * (KVR + ROPE_D) + KVR + 2 * i;
    const float e = src[0], o = src[1];
    g_krope[t * ROPE_D + 2 * i]     = e * c - o * s;
    g_krope[t * ROPE_D + 2 * i + 1] = o * c + e * s;
}

// ---------------------------------------------------------------------------
// Causal flash attention per head: 64x64 tiles, online softmax.
//   Q: g_q[t, h*192 + d]   (already roped & concat layout)
//   K: g_kvup[t, h*256 + d] (d<128) | g_krope[t, d-128]
//   V: g_kvup[t, h*256 + 128 + d]
// Output: g_attn[t, h*128 + d]
// ---------------------------------------------------------------------------
constexpr int ATTN_SMEM_FLOATS = 192 * 65 * 2 + 64 * 128 + 64 * 65 + 64 + 64;
constexpr int ATTN_SMEM_BYTES  = ATTN_SMEM_FLOATS * 4;   // 149760

__global__ void __launch_bounds__(256) attn_kernel()
{
    extern __shared__ float sm[];
    float* Qt = sm;                       // [192][65]  (transposed, scaled)
    float* Kt = Qt + 192 * 65;            // [192][65]
    float* Vs = Kt + 192 * 65;            // [64][128]
    float* Ss = Vs + 64 * 128;            // [64][65]
    float* Al = Ss + 64 * 65;             // alpha[64]
    float* Il = Al + 64;                  // 1/l [64]

    const int tid = threadIdx.x;
    const int tx  = tid & 15;
    const int ty  = tid >> 4;
    const int qt  = blockIdx.x;           // q tile (0..31)
    const int h   = blockIdx.y;
    const int qbase = qt * 64;
    const float scale = 0.07216878364870322f;  // 1/sqrt(192)

    // Load Q tile transposed, scale folded
    for (int idx = tid; idx < 64 * 192; idx += 256) {
        const int r = idx / 192, d = idx % 192;
        Qt[d * 65 + r] = g_q[(size_t)(qbase + r) * (NH * QKD) + h * QKD + d] * scale;
    }

    float m_r = -INFINITY, l_r = 0.f;     // row stats live in threads 0..63
    float o[4][8];
#pragma unroll
    for (int i = 0; i < 4; i++)
#pragma unroll
        for (int j = 0; j < 8; j++) o[i][j] = 0.f;

    for (int kt = 0; kt <= qt; kt++) {
        const int kbase = kt * 64;
        __syncthreads();   // previous tile fully consumed (also fences Qt load on first iter)

        for (int idx = tid; idx < 64 * 192; idx += 256) {
            const int r = idx / 192, d = idx % 192;
            const float v = (d < NOPE)
                ? g_kvup[(size_t)(kbase + r) * (NH * KVUP_D) + h * KVUP_D + d]
                : g_krope[(size_t)(kbase + r) * ROPE_D + (d - NOPE)];
            Kt[d * 65 + r] = v;
        }
        for (int idx = tid; idx < 64 * 128; idx += 256) {
            const int r = idx >> 7, d = idx & 127;
            Vs[r * 128 + d] =
                g_kvup[(size_t)(kbase + r) * (NH * KVUP_D) + h * KVUP_D + NOPE + d];
        }
        __syncthreads();

        // S tile = (scaled Q) K^T — 4x4 micro-tile per thread
        float sacc[4][4];
#pragma unroll
        for (int i = 0; i < 4; i++)
#pragma unroll
            for (int j = 0; j < 4; j++) sacc[i][j] = 0.f;
        for (int d = 0; d < 192; d++) {
            float qa[4], kb[4];
#pragma unroll
            for (int i = 0; i < 4; i++) qa[i] = Qt[d * 65 + ty * 4 + i];
#pragma unroll
            for (int j = 0; j < 4; j++) kb[j] = Kt[d * 65 + tx * 4 + j];
#pragma unroll
            for (int i = 0; i < 4; i++)
#pragma unroll
                for (int j = 0; j < 4; j++)
                    sacc[i][j] = fmaf(qa[i], kb[j], sacc[i][j]);
        }
#pragma unroll
        for (int i = 0; i < 4; i++)
#pragma unroll
            for (int j = 0; j < 4; j++)
                Ss[(ty * 4 + i) * 65 + tx * 4 + j] = sacc[i][j];
        __syncthreads();

        // Online softmax: thread r handles row r (r < 64)
        if (tid < 64) {
            const int r = tid;
            const int lim = (kt == qt) ? r : 63;     // causal column limit
            float mloc = m_r;
            for (int c = 0; c <= lim; c++) mloc = fmaxf(mloc, Ss[r * 65 + c]);
            const float alpha = expf(m_r - mloc);    // 0 on first tile (m_r=-inf)
            float rs = 0.f;
            for (int c = 0; c < 64; c++) {
                const float p = (c <= lim) ? expf(Ss[r * 65 + c] - mloc) : 0.f;
                Ss[r * 65 + c] = p;
                rs += p;
            }
            l_r = fmaf(l_r, alpha, rs);
            m_r = mloc;
            Al[r] = alpha;
        }
        __syncthreads();

        // O = O*alpha + P @ V
        float al[4];
#pragma unroll
        for (int i = 0; i < 4; i++) al[i] = Al[ty * 4 + i];
#pragma unroll
        for (int i = 0; i < 4; i++)
#pragma unroll
            for (int j = 0; j < 8; j++) o[i][j] *= al[i];
        for (int k2 = 0; k2 < 64; k2++) {
            float pv[4], vv[8];
#pragma unroll
            for (int i = 0; i < 4; i++) pv[i] = Ss[(ty * 4 + i) * 65 + k2];
#pragma unroll
            for (int j = 0; j < 8; j++) vv[j] = Vs[k2 * 128 + tx * 8 + j];
#pragma unroll
            for (int i = 0; i < 4; i++)
#pragma unroll
                for (int j = 0; j < 8; j++)
                    o[i][j] = fmaf(pv[i], vv[j], o[i][j]);
        }
    }

    if (tid < 64) Il[tid] = 1.f / l_r;
    __syncthreads();
#pragma unroll
    for (int i = 0; i < 4; i++) {
        const int r = qbase + ty * 4 + i;
        const float inv = Il[ty * 4 + i];
#pragma unroll
        for (int j = 0; j < 8; j++)
            g_attn[(size_t)r * (NH * VDIM) + h * VDIM + tx * 8 + j] = o[i][j] * inv;
    }
}

// ---------------------------------------------------------------------------
// Launch
// ---------------------------------------------------------------------------
static inline void launch_gemm(const float* A, const float* B, float* C,
                               int M, int N, int K)
{
    dim3 grid((N + 127) / 128, M / 128);
    gemm_nt_kernel<<<grid, 256>>>(A, B, C, M, N, K);
}

extern "C" void kernel_launch(void* const* d_in, const int* in_sizes, int n_in,
                              void* d_out, int out_size)
{
    const float* x         = (const float*)d_in[0];
    const float* w_q_down  = (const float*)d_in[1];
    const float* q_norm_w  = (const float*)d_in[2];
    const float* w_q_up    = (const float*)d_in[3];
    const float* w_kv_down = (const float*)d_in[4];
    const float* kv_norm_w = (const float*)d_in[5];
    const float* w_kv_up   = (const float*)d_in[6];
    const float* w_o       = (const float*)d_in[7];
    float* out = (float*)d_out;

    float *cq, *q, *kv, *ckv, *kvup, *attn;
    cudaGetSymbolAddress((void**)&cq,   g_cq);
    cudaGetSymbolAddress((void**)&q,    g_q);
    cudaGetSymbolAddress((void**)&kv,   g_kv);
    cudaGetSymbolAddress((void**)&ckv,  g_ckv);
    cudaGetSymbolAddress((void**)&kvup, g_kvup);
    cudaGetSymbolAddress((void**)&attn, g_attn);

    cudaFuncSetAttribute(attn_kernel,
                         cudaFuncAttributeMaxDynamicSharedMemorySize,
                         ATTN_SMEM_BYTES);

    // 1. c_q_pre = x @ w_q_down.T               [2048, 1536]
    launch_gemm(x, w_q_down, cq, SEQ, QR, DIM);
    // 2. c_q = rmsnorm(c_q_pre) (in place)
    rmsnorm_kernel<<<SEQ, 256>>>(cq, cq, q_norm_w, QR, QR, QR);
    // 3. q = c_q @ w_q_up.T                     [2048, 3072]
    launch_gemm(cq, w_q_up, q, SEQ, NH * QKD, QR);
    // 4. kv = x @ w_kv_down.T                   [2048, 576]
    launch_gemm(x, w_kv_down, kv, SEQ, KVR + ROPE_D, DIM);
    // 5. c_kv = rmsnorm(kv[:, :512])
    rmsnorm_kernel<<<SEQ, 256>>>(kv, ckv, kv_norm_w, KVR, KVR + ROPE_D, KVR);
    // 6. RoPE tables
    rope_tables_kernel<<<(SEQ * 32 + 255) / 256, 256>>>();
    // 7. RoPE on q (in place) and k_rope
    rope_q_kernel<<<(SEQ * NH * 32 + 255) / 256, 256>>>();
    rope_k_kernel<<<(SEQ * 32 + 255) / 256, 256>>>();
    // 8. kv_up = c_kv @ w_kv_up.T               [2048, 4096]
    launch_gemm(ckv, w_kv_up, kvup, SEQ, NH * KVUP_D, KVR);
    // 9. causal attention per head -> g_attn    [2048, 2048]
    attn_kernel<<<dim3(SEQ / 64, NH), 256, ATTN_SMEM_BYTES>>>();
    // 10. out = attn @ w_o.T                    [2048, 2048]
    launch_gemm(attn, w_o, out, SEQ, DIM, NH * VDIM);
}

// round 2
// speedup vs baseline: 1.6152x; 1.6152x over previous
#include <cuda_runtime.h>
#include <cuda_bf16.h>
#include <math.h>
#include <stdint.h>

// ---------------------------------------------------------------------------
// Problem constants
// ---------------------------------------------------------------------------
constexpr int SEQ    = 2048;
constexpr int DIM    = 2048;
constexpr int NH     = 16;
constexpr int QR     = 1536;   // Q_RANK
constexpr int KVR    = 512;    // KV_RANK
constexpr int ROPE_D = 64;
constexpr int NOPE   = 128;
constexpr int VDIM   = 128;
constexpr int QKD    = NOPE + ROPE_D;          // 192
constexpr int KVUP_D = NOPE + VDIM;            // 256
constexpr float EPSF = 1e-6f;

// ---------------------------------------------------------------------------
// Scratch (device globals: allocation-free)
// ---------------------------------------------------------------------------
__device__ __align__(256) float g_cq   [SEQ * QR];
__device__ __align__(256) float g_q    [SEQ * NH * QKD];
__device__ __align__(256) float g_kv   [SEQ * (KVR + ROPE_D)];
__device__ __align__(256) float g_ckv  [SEQ * KVR];
__device__ __align__(256) float g_krope[SEQ * ROPE_D];
__device__ __align__(256) float g_kvup [SEQ * NH * KVUP_D];
__device__ __align__(256) float g_attn [SEQ * NH * VDIM];
__device__ __align__(256) float g_cos  [SEQ * (ROPE_D / 2)];
__device__ __align__(256) float g_sin  [SEQ * (ROPE_D / 2)];

// ---------------------------------------------------------------------------
// tf32 helpers
// ---------------------------------------------------------------------------
__device__ __forceinline__ uint32_t f2tf32(float f) {
    uint32_t u;
    asm("cvt.rna.tf32.f32 %0, %1;" : "=r"(u) : "f"(f));
    return u;
}

// ---------------------------------------------------------------------------
// Tensor-core NT GEMM: C[M,N] = A[M,K] * B[N,K]^T (row-major, K-contiguous)
// mma.sync m16n8k8 tf32, fp32 accumulate.
// Block 128x128x16, 8 warps each 64x32. cp.async double-buffered.
// Requirements: M%128==0, K%16==0, N even (ragged N handled by predication).
// ---------------------------------------------------------------------------
constexpr int GBM = 128, GBN = 128, GBK = 16, GLDS = 20;  // smem stride 20: conflict-free

__global__ void __launch_bounds__(256) gemm_tf32_kernel(
    const float* __restrict__ A, const float* __restrict__ B,
    float* __restrict__ C, int M, int N, int K)
{
    __shared__ float As[2][GBM * GLDS];
    __shared__ float Bs[2][GBN * GLDS];

    const int tid  = threadIdx.x;
    const int warp = tid >> 5;
    const int lane = tid & 31;
    const int g    = lane >> 2;      // group id 0..7
    const int tg   = lane & 3;       // thread-in-group 0..3
    const int wm   = (warp & 1) * 64;
    const int wn   = (warp >> 1) * 32;
    const int bm0  = blockIdx.y * GBM;
    const int bn0  = blockIdx.x * GBN;

    const uint32_t sA0 = (uint32_t)__cvta_generic_to_shared(&As[0][0]);
    const uint32_t sB0 = (uint32_t)__cvta_generic_to_shared(&Bs[0][0]);

    // 512 16B-chunks per operand tile; 2 per thread.
    const int row0 = tid >> 1;                 // unused helper removed below
    (void)row0;

    auto load_tiles = [&](int buf, int k0) {
        const uint32_t sA = sA0 + buf * (GBM * GLDS * 4);
        const uint32_t sB = sB0 + buf * (GBN * GLDS * 4);
#pragma unroll
        for (int i = 0; i < 2; i++) {
            const int c   = tid + i * 256;     // 0..511
            const int row = c >> 2;
            const int seg = c & 3;
            const uint32_t da = sA + (row * GLDS + seg * 4) * 4;
            const float* ga = A + (size_t)(bm0 + row) * K + k0 + seg * 4;
            asm volatile("cp.async.cg.shared.global [%0], [%1], 16;"
                         :: "r"(da), "l"(ga));
            const int rb = bn0 + row;
            const int ok = (rb < N) ? 16 : 0;
            const float* gb = B + (size_t)(ok ? rb : 0) * K + k0 + seg * 4;
            const uint32_t db = sB + (row * GLDS + seg * 4) * 4;
            asm volatile("cp.async.cg.shared.global [%0], [%1], 16, %2;"
                         :: "r"(db), "l"(gb), "r"(ok));
        }
    };

    float acc[4][4][4];
#pragma unroll
    for (int mt = 0; mt < 4; mt++)
#pragma unroll
        for (int nt = 0; nt < 4; nt++)
#pragma unroll
            for (int v = 0; v < 4; v++) acc[mt][nt][v] = 0.f;

    const int nk = K / GBK;
    load_tiles(0, 0);
    asm volatile("cp.async.commit_group;");

    for (int kt = 0; kt < nk; kt++) {
        const int cur = kt & 1;
        asm volatile("cp.async.wait_group 0;");
        __syncthreads();
        if (kt + 1 < nk) {
            load_tiles(cur ^ 1, (kt + 1) * GBK);
            asm volatile("cp.async.commit_group;");
        }
        const float* sa = &As[cur][0];
        const float* sb = &Bs[cur][0];

#pragma unroll
        for (int k8 = 0; k8 < GBK; k8 += 8) {
            uint32_t af[4][4], bf[4][2];
#pragma unroll
            for (int mt = 0; mt < 4; mt++) {
                const int r = wm + mt * 16 + g;
                af[mt][0] = f2tf32(sa[r       * GLDS + k8 + tg]);
                af[mt][1] = f2tf32(sa[(r + 8) * GLDS + k8 + tg]);
                af[mt][2] = f2tf32(sa[r       * GLDS + k8 + tg + 4]);
                af[mt][3] = f2tf32(sa[(r + 8) * GLDS + k8 + tg + 4]);
            }
#pragma unroll
            for (int nt = 0; nt < 4; nt++) {
                const int rn = wn + nt * 8 + g;
                bf[nt][0] = f2tf32(sb[rn * GLDS + k8 + tg]);
                bf[nt][1] = f2tf32(sb[rn * GLDS + k8 + tg + 4]);
            }
#pragma unroll
            for (int mt = 0; mt < 4; mt++)
#pragma unroll
                for (int nt = 0; nt < 4; nt++) {
                    asm volatile(
                        "mma.sync.aligned.m16n8k8.row.col.f32.tf32.tf32.f32 "
                        "{%0,%1,%2,%3},{%4,%5,%6,%7},{%8,%9},{%0,%1,%2,%3};"
                        : "+f"(acc[mt][nt][0]), "+f"(acc[mt][nt][1]),
                          "+f"(acc[mt][nt][2]), "+f"(acc[mt][nt][3])
                        : "r"(af[mt][0]), "r"(af[mt][1]),
                          "r"(af[mt][2]), "r"(af[mt][3]),
                          "r"(bf[nt][0]), "r"(bf[nt][1]));
                }
        }
        __syncthreads();
    }

    // Epilogue: c0,c1 at (row, 2tg..2tg+1); c2,c3 at row+8.
#pragma unroll
    for (int mt = 0; mt < 4; mt++) {
        const int r0 = bm0 + wm + mt * 16 + g;
#pragma unroll
        for (int nt = 0; nt < 4; nt++) {
            const int cc = bn0 + wn + nt * 8 + tg * 2;
            if (cc < N) {
                *reinterpret_cast<float2*>(&C[(size_t)r0 * N + cc]) =
                    make_float2(acc[mt][nt][0], acc[mt][nt][1]);
                *reinterpret_cast<float2*>(&C[(size_t)(r0 + 8) * N + cc]) =
                    make_float2(acc[mt][nt][2], acc[mt][nt][3]);
            }
        }
    }
}

// ---------------------------------------------------------------------------
// RMSNorm
// ---------------------------------------------------------------------------
__global__ void __launch_bounds__(256) rmsnorm_kernel(
    const float* __restrict__ src, float* __restrict__ dst,
    const float* __restrict__ w, int R, int sstride, int dstride)
{
    const int row = blockIdx.x;
    const float* s = src + (size_t)row * sstride;
    float* d = dst + (size_t)row * dstride;

    float sum = 0.f;
    for (int i = threadIdx.x; i < R; i += 256) {
        float v = s[i];
        sum = fmaf(v, v, sum);
    }
    __shared__ float red[8];
#pragma unroll
    for (int o = 16; o; o >>= 1) sum += __shfl_down_sync(0xffffffffu, sum, o);
    if ((threadIdx.x & 31) == 0) red[threadIdx.x >> 5] = sum;
    __syncthreads();
    if (threadIdx.x < 8) {
        float v = red[threadIdx.x];
#pragma unroll
        for (int o = 4; o; o >>= 1) v += __shfl_down_sync(0xffu, v, o);
        if (threadIdx.x == 0) red[0] = v;
    }
    __syncthreads();
    const float mean = red[0] / (float)R;
    const float r = rsqrtf(mean + EPSF);
    for (int i = threadIdx.x; i < R; i += 256)
        d[i] = s[i] * r * w[i];
}

// ---------------------------------------------------------------------------
// RoPE
// ---------------------------------------------------------------------------
__global__ void rope_tables_kernel()
{
    const int idx = blockIdx.x * blockDim.x + threadIdx.x;
    if (idx >= SEQ * (ROPE_D / 2)) return;
    const int t = idx / (ROPE_D / 2);
    const int i = idx % (ROPE_D / 2);
    const double freq = pow(500000.0, -(double)i / 32.0);
    const float ang = (float)t * (float)freq;
    g_cos[idx] = cosf(ang);
    g_sin[idx] = sinf(ang);
}

__global__ void rope_q_kernel()
{
    const int idx = blockIdx.x * blockDim.x + threadIdx.x;
    if (idx >= SEQ * NH * (ROPE_D / 2)) return;
    const int i  = idx & 31;
    const int th = idx >> 5;
    const int h  = th % NH;
    const int t  = th / NH;
    const float c = g_cos[t * 32 + i];
    const float s = g_sin[t * 32 + i];
    float* p = g_q + (size_t)t * (NH * QKD) + h * QKD + NOPE + 2 * i;
    const float e = p[0], o = p[1];
    p[0] = e * c - o * s;
    p[1] = o * c + e * s;
}

__global__ void rope_k_kernel()
{
    const int idx = blockIdx.x * blockDim.x + threadIdx.x;
    if (idx >= SEQ * (ROPE_D / 2)) return;
    const int i = idx & 31;
    const int t = idx >> 5;
    const float c = g_cos[t * 32 + i];
    const float s = g_sin[t * 32 + i];
    const float* src = g_kv + (size_t)t * (KVR + ROPE_D) + KVR + 2 * i;
    const float e = src[0], o = src[1];
    g_krope[t * ROPE_D + 2 * i]     = e * c - o * s;
    g_krope[t * ROPE_D + 2 * i + 1] = o * c + e * s;
}

// ---------------------------------------------------------------------------
// Causal flash attention (fp32 SIMT, 64x64 tiles) — unchanged from R1
// ---------------------------------------------------------------------------
constexpr int ATTN_SMEM_FLOATS = 192 * 65 * 2 + 64 * 128 + 64 * 65 + 64 + 64;
constexpr int ATTN_SMEM_BYTES  = ATTN_SMEM_FLOATS * 4;

__global__ void __launch_bounds__(256) attn_kernel()
{
    extern __shared__ float sm[];
    float* Qt = sm;
    float* Kt = Qt + 192 * 65;
    float* Vs = Kt + 192 * 65;
    float* Ss = Vs + 64 * 128;
    float* Al = Ss + 64 * 65;
    float* Il = Al + 64;

    const int tid = threadIdx.x;
    const int tx  = tid & 15;
    const int ty  = tid >> 4;
    const int qt  = blockIdx.x;
    const int h   = blockIdx.y;
    const int qbase = qt * 64;
    const float scale = 0.07216878364870322f;  // 1/sqrt(192)

    for (int idx = tid; idx < 64 * 192; idx += 256) {
        const int r = idx / 192, d = idx % 192;
        Qt[d * 65 + r] = g_q[(size_t)(qbase + r) * (NH * QKD) + h * QKD + d] * scale;
    }

    float m_r = -INFINITY, l_r = 0.f;
    float o[4][8];
#pragma unroll
    for (int i = 0; i < 4; i++)
#pragma unroll
        for (int j = 0; j < 8; j++) o[i][j] = 0.f;

    for (int kt = 0; kt <= qt; kt++) {
        const int kbase = kt * 64;
        __syncthreads();

        for (int idx = tid; idx < 64 * 192; idx += 256) {
            const int r = idx / 192, d = idx % 192;
            const float v = (d < NOPE)
                ? g_kvup[(size_t)(kbase + r) * (NH * KVUP_D) + h * KVUP_D + d]
                : g_krope[(size_t)(kbase + r) * ROPE_D + (d - NOPE)];
            Kt[d * 65 + r] = v;
        }
        for (int idx = tid; idx < 64 * 128; idx += 256) {
            const int r = idx >> 7, d = idx & 127;
            Vs[r * 128 + d] =
                g_kvup[(size_t)(kbase + r) * (NH * KVUP_D) + h * KVUP_D + NOPE + d];
        }
        __syncthreads();

        float sacc[4][4];
#pragma unroll
        for (int i = 0; i < 4; i++)
#pragma unroll
            for (int j = 0; j < 4; j++) sacc[i][j] = 0.f;
        for (int d = 0; d < 192; d++) {
            float qa[4], kb[4];
#pragma unroll
            for (int i = 0; i < 4; i++) qa[i] = Qt[d * 65 + ty * 4 + i];
#pragma unroll
            for (int j = 0; j < 4; j++) kb[j] = Kt[d * 65 + tx * 4 + j];
#pragma unroll
            for (int i = 0; i < 4; i++)
#pragma unroll
                for (int j = 0; j < 4; j++)
                    sacc[i][j] = fmaf(qa[i], kb[j], sacc[i][j]);
        }
#pragma unroll
        for (int i = 0; i < 4; i++)
#pragma unroll
            for (int j = 0; j < 4; j++)
                Ss[(ty * 4 + i) * 65 + tx * 4 + j] = sacc[i][j];
        __syncthreads();

        if (tid < 64) {
            const int r = tid;
            const int lim = (kt == qt) ? r : 63;
            float mloc = m_r;
            for (int c = 0; c <= lim; c++) mloc = fmaxf(mloc, Ss[r * 65 + c]);
            const float alpha = expf(m_r - mloc);
            float rs = 0.f;
            for (int c = 0; c < 64; c++) {
                const float p = (c <= lim) ? expf(Ss[r * 65 + c] - mloc) : 0.f;
                Ss[r * 65 + c] = p;
                rs += p;
            }
            l_r = fmaf(l_r, alpha, rs);
            m_r = mloc;
            Al[r] = alpha;
        }
        __syncthreads();

        float al[4];
#pragma unroll
        for (int i = 0; i < 4; i++) al[i] = Al[ty * 4 + i];
#pragma unroll
        for (int i = 0; i < 4; i++)
#pragma unroll
            for (int j = 0; j < 8; j++) o[i][j] *= al[i];
        for (int k2 = 0; k2 < 64; k2++) {
            float pv[4], vv[8];
#pragma unroll
            for (int i = 0; i < 4; i++) pv[i] = Ss[(ty * 4 + i) * 65 + k2];
#pragma unroll
            for (int j = 0; j < 8; j++) vv[j] = Vs[k2 * 128 + tx * 8 + j];
#pragma unroll
            for (int i = 0; i < 4; i++)
#pragma unroll
                for (int j = 0; j < 8; j++)
                    o[i][j] = fmaf(pv[i], vv[j], o[i][j]);
        }
    }

    if (tid < 64) Il[tid] = 1.f / l_r;
    __syncthreads();
#pragma unroll
    for (int i = 0; i < 4; i++) {
        const int r = qbase + ty * 4 + i;
        const float inv = Il[ty * 4 + i];
#pragma unroll
        for (int j = 0; j < 8; j++)
            g_attn[(size_t)r * (NH * VDIM) + h * VDIM + tx * 8 + j] = o[i][j] * inv;
    }
}

// ---------------------------------------------------------------------------
// Launch
// ---------------------------------------------------------------------------
static inline void launch_gemm(const float* A, const float* B, float* C,
                               int M, int N, int K)
{
    dim3 grid((N + GBN - 1) / GBN, M / GBM);
    gemm_tf32_kernel<<<grid, 256>>>(A, B, C, M, N, K);
}

extern "C" void kernel_launch(void* const* d_in, const int* in_sizes, int n_in,
                              void* d_out, int out_size)
{
    const float* x         = (const float*)d_in[0];
    const float* w_q_down  = (const float*)d_in[1];
    const float* q_norm_w  = (const float*)d_in[2];
    const float* w_q_up    = (const float*)d_in[3];
    const float* w_kv_down = (const float*)d_in[4];
    const float* kv_norm_w = (const float*)d_in[5];
    const float* w_kv_up   = (const float*)d_in[6];
    const float* w_o       = (const float*)d_in[7];
    float* out = (float*)d_out;

    float *cq, *q, *kv, *ckv, *kvup, *attn;
    cudaGetSymbolAddress((void**)&cq,   g_cq);
    cudaGetSymbolAddress((void**)&q,    g_q);
    cudaGetSymbolAddress((void**)&kv,   g_kv);
    cudaGetSymbolAddress((void**)&ckv,  g_ckv);
    cudaGetSymbolAddress((void**)&kvup, g_kvup);
    cudaGetSymbolAddress((void**)&attn, g_attn);

    cudaFuncSetAttribute(attn_kernel,
                         cudaFuncAttributeMaxDynamicSharedMemorySize,
                         ATTN_SMEM_BYTES);

    // 1. c_q_pre = x @ w_q_down.T               [2048, 1536]
    launch_gemm(x, w_q_down, cq, SEQ, QR, DIM);
    // 2. c_q = rmsnorm(c_q_pre) (in place)
    rmsnorm_kernel<<<SEQ, 256>>>(cq, cq, q_norm_w, QR, QR, QR);
    // 3. q = c_q @ w_q_up.T                     [2048, 3072]
    launch_gemm(cq, w_q_up, q, SEQ, NH * QKD, QR);
    // 4. kv = x @ w_kv_down.T                   [2048, 576]
    launch_gemm(x, w_kv_down, kv, SEQ, KVR + ROPE_D, DIM);
    // 5. c_kv = rmsnorm(kv[:, :512])
    rmsnorm_kernel<<<SEQ, 256>>>(kv, ckv, kv_norm_w, KVR, KVR + ROPE_D, KVR);
    // 6. RoPE tables
    rope_tables_kernel<<<(SEQ * 32 + 255) / 256, 256>>>();
    // 7. RoPE on q (in place) and k_rope
    rope_q_kernel<<<(SEQ * NH * 32 + 255) / 256, 256>>>();
    rope_k_kernel<<<(SEQ * 32 + 255) / 256, 256>>>();
    // 8. kv_up = c_kv @ w_kv_up.T               [2048, 4096]
    launch_gemm(ckv, w_kv_up, kvup, SEQ, NH * KVUP_D, KVR);
    // 9. causal attention per head -> g_attn    [2048, 2048]
    attn_kernel<<<dim3(SEQ / 64, NH), 256, ATTN_SMEM_BYTES>>>();
    // 10. out = attn @ w_o.T                    [2048, 2048]
    launch_gemm(attn, w_o, out, SEQ, DIM, NH * VDIM);
}

// round 3
// speedup vs baseline: 2.9499x; 1.8264x over previous
#include <cuda_runtime.h>
#include <cuda_bf16.h>
#include <math.h>
#include <stdint.h>

// ---------------------------------------------------------------------------
// Problem constants
// ---------------------------------------------------------------------------
constexpr int SEQ    = 2048;
constexpr int DIM    = 2048;
constexpr int NH     = 16;
constexpr int QR     = 1536;
constexpr int KVR    = 512;
constexpr int ROPE_D = 64;
constexpr int NOPE   = 128;
constexpr int VDIM   = 128;
constexpr int QKD    = NOPE + ROPE_D;          // 192
constexpr int KVUP_D = NOPE + VDIM;            // 256
constexpr float EPSF = 1e-6f;

// ---------------------------------------------------------------------------
// Scratch (device globals: allocation-free)
// ---------------------------------------------------------------------------
__device__ __align__(256) float g_cq   [SEQ * QR];
__device__ __align__(256) float g_q    [SEQ * NH * QKD];
__device__ __align__(256) float g_kv   [SEQ * (KVR + ROPE_D)];
__device__ __align__(256) float g_ckv  [SEQ * KVR];
__device__ __align__(256) float g_krope[SEQ * ROPE_D];
__device__ __align__(256) float g_kvup [SEQ * NH * KVUP_D];
__device__ __align__(256) float g_attn [SEQ * NH * VDIM];
__device__ __align__(256) float g_cos  [SEQ * (ROPE_D / 2)];
__device__ __align__(256) float g_sin  [SEQ * (ROPE_D / 2)];

// ---------------------------------------------------------------------------
// tf32 helper
// ---------------------------------------------------------------------------
__device__ __forceinline__ uint32_t f2tf32(float f) {
    uint32_t u;
    asm("cvt.rna.tf32.f32 %0, %1;" : "=r"(u) : "f"(f));
    return u;
}

#define MMA_TF32(D0,D1,D2,D3,A0,A1,A2,A3,B0,B1)                              \
    asm volatile(                                                            \
        "mma.sync.aligned.m16n8k8.row.col.f32.tf32.tf32.f32 "                \
        "{%0,%1,%2,%3},{%4,%5,%6,%7},{%8,%9},{%0,%1,%2,%3};"                 \
        : "+f"(D0), "+f"(D1), "+f"(D2), "+f"(D3)                             \
        : "r"(A0), "r"(A1), "r"(A2), "r"(A3), "r"(B0), "r"(B1))

// ---------------------------------------------------------------------------
// Tensor-core NT GEMM (unchanged from R2)
// ---------------------------------------------------------------------------
constexpr int GBM = 128, GBN = 128, GBK = 16, GLDS = 20;

__global__ void __launch_bounds__(256) gemm_tf32_kernel(
    const float* __restrict__ A, const float* __restrict__ B,
    float* __restrict__ C, int M, int N, int K)
{
    __shared__ float As[2][GBM * GLDS];
    __shared__ float Bs[2][GBN * GLDS];

    const int tid  = threadIdx.x;
    const int warp = tid >> 5;
    const int lane = tid & 31;
    const int g    = lane >> 2;
    const int tg   = lane & 3;
    const int wm   = (warp & 1) * 64;
    const int wn   = (warp >> 1) * 32;
    const int bm0  = blockIdx.y * GBM;
    const int bn0  = blockIdx.x * GBN;

    const uint32_t sA0 = (uint32_t)__cvta_generic_to_shared(&As[0][0]);
    const uint32_t sB0 = (uint32_t)__cvta_generic_to_shared(&Bs[0][0]);

    auto load_tiles = [&](int buf, int k0) {
        const uint32_t sA = sA0 + buf * (GBM * GLDS * 4);
        const uint32_t sB = sB0 + buf * (GBN * GLDS * 4);
#pragma unroll
        for (int i = 0; i < 2; i++) {
            const int c   = tid + i * 256;
            const int row = c >> 2;
            const int seg = c & 3;
            const uint32_t da = sA + (row * GLDS + seg * 4) * 4;
            const float* ga = A + (size_t)(bm0 + row) * K + k0 + seg * 4;
            asm volatile("cp.async.cg.shared.global [%0], [%1], 16;"
                         :: "r"(da), "l"(ga));
            const int rb = bn0 + row;
            const int ok = (rb < N) ? 16 : 0;
            const float* gb = B + (size_t)(ok ? rb : 0) * K + k0 + seg * 4;
            const uint32_t db = sB + (row * GLDS + seg * 4) * 4;
            asm volatile("cp.async.cg.shared.global [%0], [%1], 16, %2;"
                         :: "r"(db), "l"(gb), "r"(ok));
        }
    };

    float acc[4][4][4];
#pragma unroll
    for (int mt = 0; mt < 4; mt++)
#pragma unroll
        for (int nt = 0; nt < 4; nt++)
#pragma unroll
            for (int v = 0; v < 4; v++) acc[mt][nt][v] = 0.f;

    const int nk = K / GBK;
    load_tiles(0, 0);
    asm volatile("cp.async.commit_group;");

    for (int kt = 0; kt < nk; kt++) {
        const int cur = kt & 1;
        asm volatile("cp.async.wait_group 0;");
        __syncthreads();
        if (kt + 1 < nk) {
            load_tiles(cur ^ 1, (kt + 1) * GBK);
            asm volatile("cp.async.commit_group;");
        }
        const float* sa = &As[cur][0];
        const float* sb = &Bs[cur][0];

#pragma unroll
        for (int k8 = 0; k8 < GBK; k8 += 8) {
            uint32_t af[4][4], bf[4][2];
#pragma unroll
            for (int mt = 0; mt < 4; mt++) {
                const int r = wm + mt * 16 + g;
                af[mt][0] = f2tf32(sa[r       * GLDS + k8 + tg]);
                af[mt][1] = f2tf32(sa[(r + 8) * GLDS + k8 + tg]);
                af[mt][2] = f2tf32(sa[r       * GLDS + k8 + tg + 4]);
                af[mt][3] = f2tf32(sa[(r + 8) * GLDS + k8 + tg + 4]);
            }
#pragma unroll
            for (int nt = 0; nt < 4; nt++) {
                const int rn = wn + nt * 8 + g;
                bf[nt][0] = f2tf32(sb[rn * GLDS + k8 + tg]);
                bf[nt][1] = f2tf32(sb[rn * GLDS + k8 + tg + 4]);
            }
#pragma unroll
            for (int mt = 0; mt < 4; mt++)
#pragma unroll
                for (int nt = 0; nt < 4; nt++)
                    MMA_TF32(acc[mt][nt][0], acc[mt][nt][1],
                             acc[mt][nt][2], acc[mt][nt][3],
                             af[mt][0], af[mt][1], af[mt][2], af[mt][3],
                             bf[nt][0], bf[nt][1]);
        }
        __syncthreads();
    }

#pragma unroll
    for (int mt = 0; mt < 4; mt++) {
        const int r0 = bm0 + wm + mt * 16 + g;
#pragma unroll
        for (int nt = 0; nt < 4; nt++) {
            const int cc = bn0 + wn + nt * 8 + tg * 2;
            if (cc < N) {
                *reinterpret_cast<float2*>(&C[(size_t)r0 * N + cc]) =
                    make_float2(acc[mt][nt][0], acc[mt][nt][1]);
                *reinterpret_cast<float2*>(&C[(size_t)(r0 + 8) * N + cc]) =
                    make_float2(acc[mt][nt][2], acc[mt][nt][3]);
            }
        }
    }
}

// ---------------------------------------------------------------------------
// RMSNorm / RoPE (unchanged)
// ---------------------------------------------------------------------------
__global__ void __launch_bounds__(256) rmsnorm_kernel(
    const float* __restrict__ src, float* __restrict__ dst,
    const float* __restrict__ w, int R, int sstride, int dstride)
{
    const int row = blockIdx.x;
    const float* s = src + (size_t)row * sstride;
    float* d = dst + (size_t)row * dstride;

    float sum = 0.f;
    for (int i = threadIdx.x; i < R; i += 256) {
        float v = s[i];
        sum = fmaf(v, v, sum);
    }
    __shared__ float red[8];
#pragma unroll
    for (int o = 16; o; o >>= 1) sum += __shfl_down_sync(0xffffffffu, sum, o);
    if ((threadIdx.x & 31) == 0) red[threadIdx.x >> 5] = sum;
    __syncthreads();
    if (threadIdx.x < 8) {
        float v = red[threadIdx.x];
#pragma unroll
        for (int o = 4; o; o >>= 1) v += __shfl_down_sync(0xffu, v, o);
        if (threadIdx.x == 0) red[0] = v;
    }
    __syncthreads();
    const float mean = red[0] / (float)R;
    const float r = rsqrtf(mean + EPSF);
    for (int i = threadIdx.x; i < R; i += 256)
        d[i] = s[i] * r * w[i];
}

__global__ void rope_tables_kernel()
{
    const int idx = blockIdx.x * blockDim.x + threadIdx.x;
    if (idx >= SEQ * (ROPE_D / 2)) return;
    const int t = idx / (ROPE_D / 2);
    const int i = idx % (ROPE_D / 2);
    const double freq = pow(500000.0, -(double)i / 32.0);
    const float ang = (float)t * (float)freq;
    g_cos[idx] = cosf(ang);
    g_sin[idx] = sinf(ang);
}

__global__ void rope_q_kernel()
{
    const int idx = blockIdx.x * blockDim.x + threadIdx.x;
    if (idx >= SEQ * NH * (ROPE_D / 2)) return;
    const int i  = idx & 31;
    const int th = idx >> 5;
    const int h  = th % NH;
    const int t  = th / NH;
    const float c = g_cos[t * 32 + i];
    const float s = g_sin[t * 32 + i];
    float* p = g_q + (size_t)t * (NH * QKD) + h * QKD + NOPE + 2 * i;
    const float e = p[0], o = p[1];
    p[0] = e * c - o * s;
    p[1] = o * c + e * s;
}

__global__ void rope_k_kernel()
{
    const int idx = blockIdx.x * blockDim.x + threadIdx.x;
    if (idx >= SEQ * (ROPE_D / 2)) return;
    const int i = idx & 31;
    const int t = idx >> 5;
    const float c = g_cos[t * 32 + i];
    const float s = g_sin[t * 32 + i];
    const float* src = g_kv + (size_t)t * (KVR + ROPE_D) + KVR + 2 * i;
    const float e = src[0], o = src[1];
    g_krope[t * ROPE_D + 2 * i]     = e * c - o * s;
    g_krope[t * ROPE_D + 2 * i + 1] = o * c + e * s;
}

// ---------------------------------------------------------------------------
// Tensor-core causal flash attention.
// CTA: 128 q-rows x 1 head, 8 warps (16 q-rows each), 64-wide K tiles.
// Smem layouts use a k-pair permutation: within each 8-dim group, order is
// (0,4,1,5,2,6,3,7) so thread tg's fragment pair (k=tg, k=tg+4) is one lds.64.
// Row strides 200 / 72 (≡8 mod 32) make fragment loads bank-conflict-free.
// ---------------------------------------------------------------------------
constexpr int QSTR = 200, VSTR = 72;
constexpr int ATT_SMEM_BYTES = (128 * QSTR + 64 * QSTR + 128 * VSTR) * 4;

__device__ __forceinline__ int kperm(int j) {  // j in 0..7
    return (j & 3) * 2 + (j >> 2);
}

__global__ void __launch_bounds__(256) attn_mma_kernel()
{
    extern __shared__ float sm[];
    float* Qs = sm;                     // [128][200]
    float* Ks = Qs + 128 * QSTR;        // [64][200]
    float* Vt = Ks + 64 * QSTR;         // [128][72]  V^T (vdim-major)

    const int tid  = threadIdx.x;
    const int warp = tid >> 5;
    const int lane = tid & 31;
    const int g    = lane >> 2;
    const int tg   = lane & 3;
    const int bx   = blockIdx.x;
    const int qt   = (bx & 1) ? (15 - (bx >> 1)) : (bx >> 1);  // balance causal load
    const int h    = blockIdx.y;
    const int qbase = qt * 128;
    const int r0   = warp * 16;
    const float scale = 0.07216878364870322f;  // 1/sqrt(192)

    // Q tile (scale folded), permuted-k layout
    for (int idx = tid; idx < 128 * 192; idx += 256) {
        const int r = idx / 192, d = idx % 192;
        const int pos = (d & ~7) + kperm(d & 7);
        Qs[r * QSTR + pos] =
            g_q[(size_t)(qbase + r) * (NH * QKD) + h * QKD + d] * scale;
    }

    float sacc[8][4];
    float oacc[16][4];
#pragma unroll
    for (int nv = 0; nv < 16; nv++)
#pragma unroll
        for (int v = 0; v < 4; v++) oacc[nv][v] = 0.f;
    float m0 = -INFINITY, m1 = -INFINITY, l0 = 0.f, l1 = 0.f;

    const int nkt = 2 * qt + 2;
    for (int kt = 0; kt < nkt; kt++) {
        const int kbase = kt * 64;
        __syncthreads();    // prev tile consumed (and Qs ready on first iter)

        // K tile: k_nope | k_rope, permuted-k layout
        for (int idx = tid; idx < 64 * 192; idx += 256) {
            const int r = idx / 192, d = idx % 192;
            const int pos = (d & ~7) + kperm(d & 7);
            const float v = (d < NOPE)
                ? g_kvup[(size_t)(kbase + r) * (NH * KVUP_D) + h * KVUP_D + d]
                : g_krope[(size_t)(kbase + r) * ROPE_D + (d - NOPE)];
            Ks[r * QSTR + pos] = v;
        }
        // V^T tile, permuted along k-pos
        for (int idx = tid; idx < 64 * 128; idx += 256) {
            const int r = idx >> 7, dv = idx & 127;
            const int pos = (r & ~7) + kperm(r & 7);
            Vt[dv * VSTR + pos] =
                g_kvup[(size_t)(kbase + r) * (NH * KVUP_D) + h * KVUP_D + NOPE + dv];
        }
        __syncthreads();

        // ---- S = (scaled Q) K^T --------------------------------------
#pragma unroll
        for (int nf = 0; nf < 8; nf++)
#pragma unroll
            for (int v = 0; v < 4; v++) sacc[nf][v] = 0.f;

#pragma unroll
        for (int f = 0; f < 24; f++) {
            const float2 qa = *reinterpret_cast<const float2*>(
                &Qs[(r0 + g) * QSTR + f * 8 + tg * 2]);
            const float2 qb = *reinterpret_cast<const float2*>(
                &Qs[(r0 + g + 8) * QSTR + f * 8 + tg * 2]);
            const uint32_t a0 = f2tf32(qa.x), a1 = f2tf32(qb.x);
            const uint32_t a2 = f2tf32(qa.y), a3 = f2tf32(qb.y);
#pragma unroll
            for (int nf = 0; nf < 8; nf++) {
                const float2 kb = *reinterpret_cast<const float2*>(
                    &Ks[(nf * 8 + g) * QSTR + f * 8 + tg * 2]);
                MMA_TF32(sacc[nf][0], sacc[nf][1], sacc[nf][2], sacc[nf][3],
                         a0, a1, a2, a3, f2tf32(kb.x), f2tf32(kb.y));
            }
        }

        // ---- causal mask (diagonal tiles only) -----------------------
        const int rg  = qbase + r0 + g;
        if (kbase + 63 > rg) {
#pragma unroll
            for (int nf = 0; nf < 8; nf++) {
                const int c0 = kbase + nf * 8 + tg * 2;
                if (c0     > rg)     sacc[nf][0] = -INFINITY;
                if (c0 + 1 > rg)     sacc[nf][1] = -INFINITY;
                if (c0     > rg + 8) sacc[nf][2] = -INFINITY;
                if (c0 + 1 > rg + 8) sacc[nf][3] = -INFINITY;
            }
        }

        // ---- online softmax ------------------------------------------
        float t0 = -INFINITY, t1 = -INFINITY;
#pragma unroll
        for (int nf = 0; nf < 8; nf++) {
            t0 = fmaxf(t0, fmaxf(sacc[nf][0], sacc[nf][1]));
            t1 = fmaxf(t1, fmaxf(sacc[nf][2], sacc[nf][3]));
        }
        t0 = fmaxf(t0, __shfl_xor_sync(0xffffffffu, t0, 1));
        t0 = fmaxf(t0, __shfl_xor_sync(0xffffffffu, t0, 2));
        t1 = fmaxf(t1, __shfl_xor_sync(0xffffffffu, t1, 1));
        t1 = fmaxf(t1, __shfl_xor_sync(0xffffffffu, t1, 2));
        const float nm0 = fmaxf(m0, t0), nm1 = fmaxf(m1, t1);
        const float al0 = __expf(m0 - nm0), al1 = __expf(m1 - nm1);
        m0 = nm0; m1 = nm1;

        float rs0 = 0.f, rs1 = 0.f;
#pragma unroll
        for (int nf = 0; nf < 8; nf++) {
            sacc[nf][0] = __expf(sacc[nf][0] - nm0);
            sacc[nf][1] = __expf(sacc[nf][1] - nm0);
            sacc[nf][2] = __expf(sacc[nf][2] - nm1);
            sacc[nf][3] = __expf(sacc[nf][3] - nm1);
            rs0 += sacc[nf][0] + sacc[nf][1];
            rs1 += sacc[nf][2] + sacc[nf][3];
        }
        rs0 += __shfl_xor_sync(0xffffffffu, rs0, 1);
        rs0 += __shfl_xor_sync(0xffffffffu, rs0, 2);
        rs1 += __shfl_xor_sync(0xffffffffu, rs1, 1);
        rs1 += __shfl_xor_sync(0xffffffffu, rs1, 2);
        l0 = l0 * al0 + rs0;
        l1 = l1 * al1 + rs1;

#pragma unroll
        for (int nv = 0; nv < 16; nv++) {
            oacc[nv][0] *= al0; oacc[nv][1] *= al0;
            oacc[nv][2] *= al1; oacc[nv][3] *= al1;
        }

        // ---- O += P @ V ----------------------------------------------
        const int src0 = (lane & ~3) | (tg >> 1);
        const int src2 = src0 + 2;
        const bool odd = (tg & 1);
#pragma unroll
        for (int f2 = 0; f2 < 8; f2++) {
            // C-frag -> A-frag rearrangement via quad shuffles
            const float x0 = __shfl_sync(0xffffffffu, sacc[f2][0], src0);
            const float x1 = __shfl_sync(0xffffffffu, sacc[f2][1], src0);
            const float x2 = __shfl_sync(0xffffffffu, sacc[f2][0], src2);
            const float x3 = __shfl_sync(0xffffffffu, sacc[f2][1], src2);
            const float y0 = __shfl_sync(0xffffffffu, sacc[f2][2], src0);
            const float y1 = __shfl_sync(0xffffffffu, sacc[f2][3], src0);
            const float y2 = __shfl_sync(0xffffffffu, sacc[f2][2], src2);
            const float y3 = __shfl_sync(0xffffffffu, sacc[f2][3], src2);
            const uint32_t a0 = f2tf32(odd ? x1 : x0);
            const uint32_t a1 = f2tf32(odd ? y1 : y0);
            const uint32_t a2 = f2tf32(odd ? x3 : x2);
            const uint32_t a3 = f2tf32(odd ? y3 : y2);
#pragma unroll
            for (int nv = 0; nv < 16; nv++) {
                const float2 vb = *reinterpret_cast<const float2*>(
                    &Vt[(nv * 8 + g) * VSTR + f2 * 8 + tg * 2]);
                MMA_TF32(oacc[nv][0], oacc[nv][1], oacc[nv][2], oacc[nv][3],
                         a0, a1, a2, a3, f2tf32(vb.x), f2tf32(vb.y));
            }
        }
    }

    // ---- epilogue ----------------------------------------------------
    const float inv0 = 1.f / l0, inv1 = 1.f / l1;
    const int rga = qbase + r0 + g;
#pragma unroll
    for (int nv = 0; nv < 16; nv++) {
        const int col = h * VDIM + nv * 8 + tg * 2;
        *reinterpret_cast<float2*>(&g_attn[(size_t)rga * (NH * VDIM) + col]) =
            make_float2(oacc[nv][0] * inv0, oacc[nv][1] * inv0);
        *reinterpret_cast<float2*>(&g_attn[(size_t)(rga + 8) * (NH * VDIM) + col]) =
            make_float2(oacc[nv][2] * inv1, oacc[nv][3] * inv1);
    }
}

// ---------------------------------------------------------------------------
// Launch
// ---------------------------------------------------------------------------
static inline void launch_gemm(const float* A, const float* B, float* C,
                               int M, int N, int K)
{
    dim3 grid((N + GBN - 1) / GBN, M / GBM);
    gemm_tf32_kernel<<<grid, 256>>>(A, B, C, M, N, K);
}

extern "C" void kernel_launch(void* const* d_in, const int* in_sizes, int n_in,
                              void* d_out, int out_size)
{
    const float* x         = (const float*)d_in[0];
    const float* w_q_down  = (const float*)d_in[1];
    const float* q_norm_w  = (const float*)d_in[2];
    const float* w_q_up    = (const float*)d_in[3];
    const float* w_kv_down = (const float*)d_in[4];
    const float* kv_norm_w = (const float*)d_in[5];
    const float* w_kv_up   = (const float*)d_in[6];
    const float* w_o       = (const float*)d_in[7];
    float* out = (float*)d_out;

    float *cq, *q, *kv, *ckv, *kvup, *attn;
    cudaGetSymbolAddress((void**)&cq,   g_cq);
    cudaGetSymbolAddress((void**)&q,    g_q);
    cudaGetSymbolAddress((void**)&kv,   g_kv);
    cudaGetSymbolAddress((void**)&ckv,  g_ckv);
    cudaGetSymbolAddress((void**)&kvup, g_kvup);
    cudaGetSymbolAddress((void**)&attn, g_attn);

    cudaFuncSetAttribute(attn_mma_kernel,
                         cudaFuncAttributeMaxDynamicSharedMemorySize,
                         ATT_SMEM_BYTES);

    // 1. c_q_pre = x @ w_q_down.T               [2048, 1536]
    launch_gemm(x, w_q_down, cq, SEQ, QR, DIM);
    // 2. c_q = rmsnorm(c_q_pre) (in place)
    rmsnorm_kernel<<<SEQ, 256>>>(cq, cq, q_norm_w, QR, QR, QR);
    // 3. q = c_q @ w_q_up.T                     [2048, 3072]
    launch_gemm(cq, w_q_up, q, SEQ, NH * QKD, QR);
    // 4. kv = x @ w_kv_down.T                   [2048, 576]
    launch_gemm(x, w_kv_down, kv, SEQ, KVR + ROPE_D, DIM);
    // 5. c_kv = rmsnorm(kv[:, :512])
    rmsnorm_kernel<<<SEQ, 256>>>(kv, ckv, kv_norm_w, KVR, KVR + ROPE_D, KVR);
    // 6. RoPE tables
    rope_tables_kernel<<<(SEQ * 32 + 255) / 256, 256>>>();
    // 7. RoPE on q (in place) and k_rope
    rope_q_kernel<<<(SEQ * NH * 32 + 255) / 256, 256>>>();
    rope_k_kernel<<<(SEQ * 32 + 255) / 256, 256>>>();
    // 8. kv_up = c_kv @ w_kv_up.T               [2048, 4096]
    launch_gemm(ckv, w_kv_up, kvup, SEQ, NH * KVUP_D, KVR);
    // 9. tensor-core causal attention -> g_attn [2048, 2048]
    attn_mma_kernel<<<dim3(SEQ / 128, NH), 256, ATT_SMEM_BYTES>>>();
    // 10. out = attn @ w_o.T                    [2048, 2048]
    launch_gemm(attn, w_o, out, SEQ, DIM, NH * VDIM);
}

// round 4
// speedup vs baseline: 2.9919x; 1.0142x over previous
#include <cuda_runtime.h>
#include <cuda_bf16.h>
#include <math.h>
#include <stdint.h>

// ---------------------------------------------------------------------------
// Problem constants
// ---------------------------------------------------------------------------
constexpr int SEQ    = 2048;
constexpr int DIM    = 2048;
constexpr int NH     = 16;
constexpr int QR     = 1536;
constexpr int KVR    = 512;
constexpr int ROPE_D = 64;
constexpr int NOPE   = 128;
constexpr int VDIM   = 128;
constexpr int QKD    = NOPE + ROPE_D;          // 192
constexpr int KVUP_D = NOPE + VDIM;            // 256
constexpr float EPSF = 1e-6f;

// ---------------------------------------------------------------------------
// Scratch (device globals: allocation-free)
// ---------------------------------------------------------------------------
__device__ __align__(256) float g_cq   [SEQ * QR];
__device__ __align__(256) float g_q    [SEQ * NH * QKD];
__device__ __align__(256) float g_kv   [SEQ * (KVR + ROPE_D)];
__device__ __align__(256) float g_ckv  [SEQ * KVR];
__device__ __align__(256) float g_krope[SEQ * ROPE_D];
__device__ __align__(256) float g_kvup [SEQ * NH * KVUP_D];
__device__ __align__(256) float g_attn [SEQ * NH * VDIM];
__device__ __align__(256) float g_cos  [SEQ * (ROPE_D / 2)];
__device__ __align__(256) float g_sin  [SEQ * (ROPE_D / 2)];

// ---------------------------------------------------------------------------
// tf32 helper
// ---------------------------------------------------------------------------
__device__ __forceinline__ uint32_t f2tf32(float f) {
    uint32_t u;
    asm("cvt.rna.tf32.f32 %0, %1;" : "=r"(u) : "f"(f));
    return u;
}

#define MMA_TF32(D0,D1,D2,D3,A0,A1,A2,A3,B0,B1)                              \
    asm volatile(                                                            \
        "mma.sync.aligned.m16n8k8.row.col.f32.tf32.tf32.f32 "                \
        "{%0,%1,%2,%3},{%4,%5,%6,%7},{%8,%9},{%0,%1,%2,%3};"                 \
        : "+f"(D0), "+f"(D1), "+f"(D2), "+f"(D3)                             \
        : "r"(A0), "r"(A1), "r"(A2), "r"(A3), "r"(B0), "r"(B1))

// ---------------------------------------------------------------------------
// Tensor-core NT GEMM: C[M,N] = A[M,K] * B[N,K]^T (row-major, K-contiguous)
// Block 128xBN x16, 8 warps each 64x(BN/4). 2 CTAs/SM for latency hiding.
// ---------------------------------------------------------------------------
constexpr int GBM = 128, GBK = 16, GLDS = 20;

template<int BN>
__global__ void __launch_bounds__(256, 2) gemm_tf32_kernel(
    const float* __restrict__ A, const float* __restrict__ B,
    float* __restrict__ C, int M, int N, int K)
{
    constexpr int NT = BN / 32;                 // n-fragments per warp
    __shared__ float As[2][GBM * GLDS];
    __shared__ float Bs[2][BN * GLDS];

    const int tid  = threadIdx.x;
    const int warp = tid >> 5;
    const int lane = tid & 31;
    const int g    = lane >> 2;
    const int tg   = lane & 3;
    const int wm   = (warp & 1) * 64;
    const int wn   = (warp >> 1) * (BN / 4);
    const int bm0  = blockIdx.y * GBM;
    const int bn0  = blockIdx.x * BN;

    const uint32_t sA0 = (uint32_t)__cvta_generic_to_shared(&As[0][0]);
    const uint32_t sB0 = (uint32_t)__cvta_generic_to_shared(&Bs[0][0]);

    auto load_tiles = [&](int buf, int k0) {
        const uint32_t sA = sA0 + buf * (GBM * GLDS * 4);
        const uint32_t sB = sB0 + buf * (BN * GLDS * 4);
#pragma unroll
        for (int i = 0; i < 2; i++) {           // A: 512 16B chunks
            const int c   = tid + i * 256;
            const int row = c >> 2;
            const int seg = c & 3;
            const uint32_t da = sA + (row * GLDS + seg * 4) * 4;
            const float* ga = A + (size_t)(bm0 + row) * K + k0 + seg * 4;
            asm volatile("cp.async.cg.shared.global [%0], [%1], 16;"
                         :: "r"(da), "l"(ga));
        }
#pragma unroll
        for (int i = 0; i < BN / 64; i++) {     // B: BN*4 chunks
            const int c   = tid + i * 256;
            const int row = c >> 2;
            const int seg = c & 3;
            const int rb  = bn0 + row;
            const int ok  = (rb < N) ? 16 : 0;
            const float* gb = B + (size_t)(ok ? rb : 0) * K + k0 + seg * 4;
            const uint32_t db = sB + (row * GLDS + seg * 4) * 4;
            asm volatile("cp.async.cg.shared.global [%0], [%1], 16, %2;"
                         :: "r"(db), "l"(gb), "r"(ok));
        }
    };

    float acc[4][NT][4];
#pragma unroll
    for (int mt = 0; mt < 4; mt++)
#pragma unroll
        for (int nt = 0; nt < NT; nt++)
#pragma unroll
            for (int v = 0; v < 4; v++) acc[mt][nt][v] = 0.f;

    const int nk = K / GBK;
    load_tiles(0, 0);
    asm volatile("cp.async.commit_group;");

    for (int kt = 0; kt < nk; kt++) {
        const int cur = kt & 1;
        asm volatile("cp.async.wait_group 0;");
        __syncthreads();
        if (kt + 1 < nk) {
            load_tiles(cur ^ 1, (kt + 1) * GBK);
            asm volatile("cp.async.commit_group;");
        }
        const float* sa = &As[cur][0];
        const float* sb = &Bs[cur][0];

#pragma unroll
        for (int k8 = 0; k8 < GBK; k8 += 8) {
            uint32_t af[4][4], bf[NT][2];
#pragma unroll
            for (int mt = 0; mt < 4; mt++) {
                const int r = wm + mt * 16 + g;
                af[mt][0] = f2tf32(sa[r       * GLDS + k8 + tg]);
                af[mt][1] = f2tf32(sa[(r + 8) * GLDS + k8 + tg]);
                af[mt][2] = f2tf32(sa[r       * GLDS + k8 + tg + 4]);
                af[mt][3] = f2tf32(sa[(r + 8) * GLDS + k8 + tg + 4]);
            }
#pragma unroll
            for (int nt = 0; nt < NT; nt++) {
                const int rn = wn + nt * 8 + g;
                bf[nt][0] = f2tf32(sb[rn * GLDS + k8 + tg]);
                bf[nt][1] = f2tf32(sb[rn * GLDS + k8 + tg + 4]);
            }
#pragma unroll
            for (int mt = 0; mt < 4; mt++)
#pragma unroll
                for (int nt = 0; nt < NT; nt++)
                    MMA_TF32(acc[mt][nt][0], acc[mt][nt][1],
                             acc[mt][nt][2], acc[mt][nt][3],
                             af[mt][0], af[mt][1], af[mt][2], af[mt][3],
                             bf[nt][0], bf[nt][1]);
        }
        __syncthreads();
    }

#pragma unroll
    for (int mt = 0; mt < 4; mt++) {
        const int r0 = bm0 + wm + mt * 16 + g;
#pragma unroll
        for (int nt = 0; nt < NT; nt++) {
            const int cc = bn0 + wn + nt * 8 + tg * 2;
            if (cc < N) {
                *reinterpret_cast<float2*>(&C[(size_t)r0 * N + cc]) =
                    make_float2(acc[mt][nt][0], acc[mt][nt][1]);
                *reinterpret_cast<float2*>(&C[(size_t)(r0 + 8) * N + cc]) =
                    make_float2(acc[mt][nt][2], acc[mt][nt][3]);
            }
        }
    }
}

// ---------------------------------------------------------------------------
// RMSNorm / RoPE (unchanged)
// ---------------------------------------------------------------------------
__global__ void __launch_bounds__(256) rmsnorm_kernel(
    const float* __restrict__ src, float* __restrict__ dst,
    const float* __restrict__ w, int R, int sstride, int dstride)
{
    const int row = blockIdx.x;
    const float* s = src + (size_t)row * sstride;
    float* d = dst + (size_t)row * dstride;

    float sum = 0.f;
    for (int i = threadIdx.x; i < R; i += 256) {
        float v = s[i];
        sum = fmaf(v, v, sum);
    }
    __shared__ float red[8];
#pragma unroll
    for (int o = 16; o; o >>= 1) sum += __shfl_down_sync(0xffffffffu, sum, o);
    if ((threadIdx.x & 31) == 0) red[threadIdx.x >> 5] = sum;
    __syncthreads();
    if (threadIdx.x < 8) {
        float v = red[threadIdx.x];
#pragma unroll
        for (int o = 4; o; o >>= 1) v += __shfl_down_sync(0xffu, v, o);
        if (threadIdx.x == 0) red[0] = v;
    }
    __syncthreads();
    const float mean = red[0] / (float)R;
    const float r = rsqrtf(mean + EPSF);
    for (int i = threadIdx.x; i < R; i += 256)
        d[i] = s[i] * r * w[i];
}

__global__ void rope_tables_kernel()
{
    const int idx = blockIdx.x * blockDim.x + threadIdx.x;
    if (idx >= SEQ * (ROPE_D / 2)) return;
    const int t = idx / (ROPE_D / 2);
    const int i = idx % (ROPE_D / 2);
    const double freq = pow(500000.0, -(double)i / 32.0);
    const float ang = (float)t * (float)freq;
    g_cos[idx] = cosf(ang);
    g_sin[idx] = sinf(ang);
}

__global__ void rope_q_kernel()
{
    const int idx = blockIdx.x * blockDim.x + threadIdx.x;
    if (idx >= SEQ * NH * (ROPE_D / 2)) return;
    const int i  = idx & 31;
    const int th = idx >> 5;
    const int h  = th % NH;
    const int t  = th / NH;
    const float c = g_cos[t * 32 + i];
    const float s = g_sin[t * 32 + i];
    float* p = g_q + (size_t)t * (NH * QKD) + h * QKD + NOPE + 2 * i;
    const float e = p[0], o = p[1];
    p[0] = e * c - o * s;
    p[1] = o * c + e * s;
}

__global__ void rope_k_kernel()
{
    const int idx = blockIdx.x * blockDim.x + threadIdx.x;
    if (idx >= SEQ * (ROPE_D / 2)) return;
    const int i = idx & 31;
    const int t = idx >> 5;
    const float c = g_cos[t * 32 + i];
    const float s = g_sin[t * 32 + i];
    const float* src = g_kv + (size_t)t * (KVR + ROPE_D) + KVR + 2 * i;
    const float e = src[0], o = src[1];
    g_krope[t * ROPE_D + 2 * i]     = e * c - o * s;
    g_krope[t * ROPE_D + 2 * i + 1] = o * c + e * s;
}

// ---------------------------------------------------------------------------
// Tensor-core causal flash attention (unchanged from R3)
// ---------------------------------------------------------------------------
constexpr int QSTR = 200, VSTR = 72;
constexpr int ATT_SMEM_BYTES = (128 * QSTR + 64 * QSTR + 128 * VSTR) * 4;

__device__ __forceinline__ int kperm(int j) {
    return (j & 3) * 2 + (j >> 2);
}

__global__ void __launch_bounds__(256) attn_mma_kernel()
{
    extern __shared__ float sm[];
    float* Qs = sm;                     // [128][200]
    float* Ks = Qs + 128 * QSTR;        // [64][200]
    float* Vt = Ks + 64 * QSTR;         // [128][72]

    const int tid  = threadIdx.x;
    const int warp = tid >> 5;
    const int lane = tid & 31;
    const int g    = lane >> 2;
    const int tg   = lane & 3;
    const int bx   = blockIdx.x;
    const int qt   = (bx & 1) ? (15 - (bx >> 1)) : (bx >> 1);
    const int h    = blockIdx.y;
    const int qbase = qt * 128;
    const int r0   = warp * 16;
    const float scale = 0.07216878364870322f;  // 1/sqrt(192)

    for (int idx = tid; idx < 128 * 192; idx += 256) {
        const int r = idx / 192, d = idx % 192;
        const int pos = (d & ~7) + kperm(d & 7);
        Qs[r * QSTR + pos] =
            g_q[(size_t)(qbase + r) * (NH * QKD) + h * QKD + d] * scale;
    }

    float sacc[8][4];
    float oacc[16][4];
#pragma unroll
    for (int nv = 0; nv < 16; nv++)
#pragma unroll
        for (int v = 0; v < 4; v++) oacc[nv][v] = 0.f;
    float m0 = -INFINITY, m1 = -INFINITY, l0 = 0.f, l1 = 0.f;

    const int nkt = 2 * qt + 2;
    for (int kt = 0; kt < nkt; kt++) {
        const int kbase = kt * 64;
        __syncthreads();

        for (int idx = tid; idx < 64 * 192; idx += 256) {
            const int r = idx / 192, d = idx % 192;
            const int pos = (d & ~7) + kperm(d & 7);
            const float v = (d < NOPE)
                ? g_kvup[(size_t)(kbase + r) * (NH * KVUP_D) + h * KVUP_D + d]
                : g_krope[(size_t)(kbase + r) * ROPE_D + (d - NOPE)];
            Ks[r * QSTR + pos] = v;
        }
        for (int idx = tid; idx < 64 * 128; idx += 256) {
            const int r = idx >> 7, dv = idx & 127;
            const int pos = (r & ~7) + kperm(r & 7);
            Vt[dv * VSTR + pos] =
                g_kvup[(size_t)(kbase + r) * (NH * KVUP_D) + h * KVUP_D + NOPE + dv];
        }
        __syncthreads();

#pragma unroll
        for (int nf = 0; nf < 8; nf++)
#pragma unroll
            for (int v = 0; v < 4; v++) sacc[nf][v] = 0.f;

#pragma unroll
        for (int f = 0; f < 24; f++) {
            const float2 qa = *reinterpret_cast<const float2*>(
                &Qs[(r0 + g) * QSTR + f * 8 + tg * 2]);
            const float2 qb = *reinterpret_cast<const float2*>(
                &Qs[(r0 + g + 8) * QSTR + f * 8 + tg * 2]);
            const uint32_t a0 = f2tf32(qa.x), a1 = f2tf32(qb.x);
            const uint32_t a2 = f2tf32(qa.y), a3 = f2tf32(qb.y);
#pragma unroll
            for (int nf = 0; nf < 8; nf++) {
                const float2 kb = *reinterpret_cast<const float2*>(
                    &Ks[(nf * 8 + g) * QSTR + f * 8 + tg * 2]);
                MMA_TF32(sacc[nf][0], sacc[nf][1], sacc[nf][2], sacc[nf][3],
                         a0, a1, a2, a3, f2tf32(kb.x), f2tf32(kb.y));
            }
        }

        const int rg  = qbase + r0 + g;
        if (kbase + 63 > rg) {
#pragma unroll
            for (int nf = 0; nf < 8; nf++) {
                const int c0 = kbase + nf * 8 + tg * 2;
                if (c0     > rg)     sacc[nf][0] = -INFINITY;
                if (c0 + 1 > rg)     sacc[nf][1] = -INFINITY;
                if (c0     > rg + 8) sacc[nf][2] = -INFINITY;
                if (c0 + 1 > rg + 8) sacc[nf][3] = -INFINITY;
            }
        }

        float t0 = -INFINITY, t1 = -INFINITY;
#pragma unroll
        for (int nf = 0; nf < 8; nf++) {
            t0 = fmaxf(t0, fmaxf(sacc[nf][0], sacc[nf][1]));
            t1 = fmaxf(t1, fmaxf(sacc[nf][2], sacc[nf][3]));
        }
        t0 = fmaxf(t0, __shfl_xor_sync(0xffffffffu, t0, 1));
        t0 = fmaxf(t0, __shfl_xor_sync(0xffffffffu, t0, 2));
        t1 = fmaxf(t1, __shfl_xor_sync(0xffffffffu, t1, 1));
        t1 = fmaxf(t1, __shfl_xor_sync(0xffffffffu, t1, 2));
        const float nm0 = fmaxf(m0, t0), nm1 = fmaxf(m1, t1);
        const float al0 = __expf(m0 - nm0), al1 = __expf(m1 - nm1);
        m0 = nm0; m1 = nm1;

        float rs0 = 0.f, rs1 = 0.f;
#pragma unroll
        for (int nf = 0; nf < 8; nf++) {
            sacc[nf][0] = __expf(sacc[nf][0] - nm0);
            sacc[nf][1] = __expf(sacc[nf][1] - nm0);
            sacc[nf][2] = __expf(sacc[nf][2] - nm1);
            sacc[nf][3] = __expf(sacc[nf][3] - nm1);
            rs0 += sacc[nf][0] + sacc[nf][1];
            rs1 += sacc[nf][2] + sacc[nf][3];
        }
        rs0 += __shfl_xor_sync(0xffffffffu, rs0, 1);
        rs0 += __shfl_xor_sync(0xffffffffu, rs0, 2);
        rs1 += __shfl_xor_sync(0xffffffffu, rs1, 1);
        rs1 += __shfl_xor_sync(0xffffffffu, rs1, 2);
        l0 = l0 * al0 + rs0;
        l1 = l1 * al1 + rs1;

#pragma unroll
        for (int nv = 0; nv < 16; nv++) {
            oacc[nv][0] *= al0; oacc[nv][1] *= al0;
            oacc[nv][2] *= al1; oacc[nv][3] *= al1;
        }

        const int src0 = (lane & ~3) | (tg >> 1);
        const int src2 = src0 + 2;
        const bool odd = (tg & 1);
#pragma unroll
        for (int f2 = 0; f2 < 8; f2++) {
            const float x0 = __shfl_sync(0xffffffffu, sacc[f2][0], src0);
            const float x1 = __shfl_sync(0xffffffffu, sacc[f2][1], src0);
            const float x2 = __shfl_sync(0xffffffffu, sacc[f2][0], src2);
            const float x3 = __shfl_sync(0xffffffffu, sacc[f2][1], src2);
            const float y0 = __shfl_sync(0xffffffffu, sacc[f2][2], src0);
            const float y1 = __shfl_sync(0xffffffffu, sacc[f2][3], src0);
            const float y2 = __shfl_sync(0xffffffffu, sacc[f2][2], src2);
            const float y3 = __shfl_sync(0xffffffffu, sacc[f2][3], src2);
            const uint32_t a0 = f2tf32(odd ? x1 : x0);
            const uint32_t a1 = f2tf32(odd ? y1 : y0);
            const uint32_t a2 = f2tf32(odd ? x3 : x2);
            const uint32_t a3 = f2tf32(odd ? y3 : y2);
#pragma unroll
            for (int nv = 0; nv < 16; nv++) {
                const float2 vb = *reinterpret_cast<const float2*>(
                    &Vt[(nv * 8 + g) * VSTR + f2 * 8 + tg * 2]);
                MMA_TF32(oacc[nv][0], oacc[nv][1], oacc[nv][2], oacc[nv][3],
                         a0, a1, a2, a3, f2tf32(vb.x), f2tf32(vb.y));
            }
        }
    }

    const float inv0 = 1.f / l0, inv1 = 1.f / l1;
    const int rga = qbase + r0 + g;
#pragma unroll
    for (int nv = 0; nv < 16; nv++) {
        const int col = h * VDIM + nv * 8 + tg * 2;
        *reinterpret_cast<float2*>(&g_attn[(size_t)rga * (NH * VDIM) + col]) =
            make_float2(oacc[nv][0] * inv0, oacc[nv][1] * inv0);
        *reinterpret_cast<float2*>(&g_attn[(size_t)(rga + 8) * (NH * VDIM) + col]) =
            make_float2(oacc[nv][2] * inv1, oacc[nv][3] * inv1);
    }
}

// ---------------------------------------------------------------------------
// Launch
// ---------------------------------------------------------------------------
static inline void launch_gemm(const float* A, const float* B, float* C,
                               int M, int N, int K)
{
    if (N >= 1024) {
        dim3 grid((N + 127) / 128, M / GBM);
        gemm_tf32_kernel<128><<<grid, 256>>>(A, B, C, M, N, K);
    } else {
        dim3 grid((N + 63) / 64, M / GBM);
        gemm_tf32_kernel<64><<<grid, 256>>>(A, B, C, M, N, K);
    }
}

extern "C" void kernel_launch(void* const* d_in, const int* in_sizes, int n_in,
                              void* d_out, int out_size)
{
    const float* x         = (const float*)d_in[0];
    const float* w_q_down  = (const float*)d_in[1];
    const float* q_norm_w  = (const float*)d_in[2];
    const float* w_q_up    = (const float*)d_in[3];
    const float* w_kv_down = (const float*)d_in[4];
    const float* kv_norm_w = (const float*)d_in[5];
    const float* w_kv_up   = (const float*)d_in[6];
    const float* w_o       = (const float*)d_in[7];
    float* out = (float*)d_out;

    float *cq, *q, *kv, *ckv, *kvup, *attn;
    cudaGetSymbolAddress((void**)&cq,   g_cq);
    cudaGetSymbolAddress((void**)&q,    g_q);
    cudaGetSymbolAddress((void**)&kv,   g_kv);
    cudaGetSymbolAddress((void**)&ckv,  g_ckv);
    cudaGetSymbolAddress((void**)&kvup, g_kvup);
    cudaGetSymbolAddress((void**)&attn, g_attn);

    cudaFuncSetAttribute(attn_mma_kernel,
                         cudaFuncAttributeMaxDynamicSharedMemorySize,
                         ATT_SMEM_BYTES);

    // 1. c_q_pre = x @ w_q_down.T               [2048, 1536]
    launch_gemm(x, w_q_down, cq, SEQ, QR, DIM);
    // 2. c_q = rmsnorm(c_q_pre) (in place)
    rmsnorm_kernel<<<SEQ, 256>>>(cq, cq, q_norm_w, QR, QR, QR);
    // 3. q = c_q @ w_q_up.T                     [2048, 3072]
    launch_gemm(cq, w_q_up, q, SEQ, NH * QKD, QR);
    // 4. kv = x @ w_kv_down.T                   [2048, 576]
    launch_gemm(x, w_kv_down, kv, SEQ, KVR + ROPE_D, DIM);
    // 5. c_kv = rmsnorm(kv[:, :512])
    rmsnorm_kernel<<<SEQ, 256>>>(kv, ckv, kv_norm_w, KVR, KVR + ROPE_D, KVR);
    // 6. RoPE tables
    rope_tables_kernel<<<(SEQ * 32 + 255) / 256, 256>>>();
    // 7. RoPE on q (in place) and k_rope
    rope_q_kernel<<<(SEQ * NH * 32 + 255) / 256, 256>>>();
    rope_k_kernel<<<(SEQ * 32 + 255) / 256, 256>>>();
    // 8. kv_up = c_kv @ w_kv_up.T               [2048, 4096]
    launch_gemm(ckv, w_kv_up, kvup, SEQ, NH * KVUP_D, KVR);
    // 9. tensor-core causal attention -> g_attn [2048, 2048]
    attn_mma_kernel<<<dim3(SEQ / 128, NH), 256, ATT_SMEM_BYTES>>>();
    // 10. out = attn @ w_o.T                    [2048, 2048]
    launch_gemm(attn, w_o, out, SEQ, DIM, NH * VDIM);
}

// round 5
// speedup vs baseline: 3.0521x; 1.0201x over previous
#include <cuda_runtime.h>
#include <cuda_bf16.h>
#include <math.h>
#include <stdint.h>

// ---------------------------------------------------------------------------
// Problem constants
// ---------------------------------------------------------------------------
constexpr int SEQ    = 2048;
constexpr int DIM    = 2048;
constexpr int NH     = 16;
constexpr int QR     = 1536;
constexpr int KVR    = 512;
constexpr int ROPE_D = 64;
constexpr int NOPE   = 128;
constexpr int VDIM   = 128;
constexpr int QKD    = NOPE + ROPE_D;          // 192
constexpr int KVUP_D = NOPE + VDIM;            // 256
constexpr float EPSF = 1e-6f;

// ---------------------------------------------------------------------------
// Scratch (device globals: allocation-free)
// ---------------------------------------------------------------------------
__device__ __align__(256) float g_cq   [SEQ * QR];
__device__ __align__(256) float g_q    [SEQ * NH * QKD];
__device__ __align__(256) float g_kv   [SEQ * (KVR + ROPE_D)];
__device__ __align__(256) float g_ckv  [SEQ * KVR];
__device__ __align__(256) float g_krope[SEQ * ROPE_D];
__device__ __align__(256) float g_kvup [SEQ * NH * KVUP_D];
__device__ __align__(256) float g_attn [SEQ * NH * VDIM];
__device__ __align__(256) float g_cos  [SEQ * (ROPE_D / 2)];
__device__ __align__(256) float g_sin  [SEQ * (ROPE_D / 2)];
// tf32-pre-rounded operand copies
__device__ __align__(256) float g_x    [SEQ * DIM];
__device__ __align__(256) float g_wqd  [QR * DIM];
__device__ __align__(256) float g_wqu  [NH * QKD * QR];
__device__ __align__(256) float g_wkvd [(KVR + ROPE_D) * DIM];
__device__ __align__(256) float g_wkvu [NH * KVUP_D * KVR];
__device__ __align__(256) float g_wo   [DIM * NH * VDIM];

// ---------------------------------------------------------------------------
// tf32 helper
// ---------------------------------------------------------------------------
__device__ __forceinline__ uint32_t f2tf32(float f) {
    uint32_t u;
    asm("cvt.rna.tf32.f32 %0, %1;" : "=r"(u) : "f"(f));
    return u;
}
__device__ __forceinline__ float round_tf32(float f) {
    return __uint_as_float(f2tf32(f));
}

#define MMA_TF32(D0,D1,D2,D3,A0,A1,A2,A3,B0,B1)                              \
    asm volatile(                                                            \
        "mma.sync.aligned.m16n8k8.row.col.f32.tf32.tf32.f32 "                \
        "{%0,%1,%2,%3},{%4,%5,%6,%7},{%8,%9},{%0,%1,%2,%3};"                 \
        : "+f"(D0), "+f"(D1), "+f"(D2), "+f"(D3)                             \
        : "r"(A0), "r"(A1), "r"(A2), "r"(A3), "r"(B0), "r"(B1))

// ---------------------------------------------------------------------------
// Elementwise tf32 pre-rounding (vectorized)
// ---------------------------------------------------------------------------
__global__ void __launch_bounds__(256) round_tf32_kernel(
    const float4* __restrict__ src, float4* __restrict__ dst, int n4)
{
    for (int i = blockIdx.x * 256 + threadIdx.x; i < n4; i += gridDim.x * 256) {
        float4 v = src[i];
        v.x = round_tf32(v.x); v.y = round_tf32(v.y);
        v.z = round_tf32(v.z); v.w = round_tf32(v.w);
        dst[i] = v;
    }
}

// ---------------------------------------------------------------------------
// Tensor-core NT GEMM: C[M,N] = A[M,K] * B[N,K]^T (row-major, K-contiguous)
// Operands MUST be tf32-pre-rounded (inner loop feeds raw bits to mma).
// Block 128 x BN x 32, 8 warps each 64 x (BN/4). Dynamic smem, 2 CTAs/SM.
// ---------------------------------------------------------------------------
constexpr int GBM = 128, GBK = 32, GST = 36;   // 32 k + 4 pad, conflict-free

template<int BN>
constexpr int gemm_smem_bytes() { return 2 * GST * (GBM + BN) * 4; }

template<int BN>
__global__ void __launch_bounds__(256, 2) gemm_tf32_kernel(
    const float* __restrict__ A, const float* __restrict__ B,
    float* __restrict__ C, int M, int N, int K)
{
    constexpr int NT = BN / 32;
    extern __shared__ float smg[];
    float* Asm = smg;                          // [2][GBM*GST]
    float* Bsm = smg + 2 * GBM * GST;          // [2][BN*GST]

    const int tid  = threadIdx.x;
    const int warp = tid >> 5;
    const int lane = tid & 31;
    const int g    = lane >> 2;
    const int tg   = lane & 3;
    const int wm   = (warp & 1) * 64;
    const int wn   = (warp >> 1) * (BN / 4);
    const int bm0  = blockIdx.y * GBM;
    const int bn0  = blockIdx.x * BN;

    const uint32_t sA0 = (uint32_t)__cvta_generic_to_shared(Asm);
    const uint32_t sB0 = (uint32_t)__cvta_generic_to_shared(Bsm);

    auto load_tiles = [&](int buf, int k0) {
        const uint32_t sA = sA0 + buf * (GBM * GST * 4);
        const uint32_t sB = sB0 + buf * (BN * GST * 4);
#pragma unroll
        for (int i = 0; i < 4; i++) {          // A: 1024 16B chunks
            const int c   = tid + i * 256;
            const int row = c >> 3;
            const int seg = c & 7;
            const uint32_t da = sA + (row * GST + seg * 4) * 4;
            const float* ga = A + (size_t)(bm0 + row) * K + k0 + seg * 4;
            asm volatile("cp.async.cg.shared.global [%0], [%1], 16;"
                         :: "r"(da), "l"(ga));
        }
#pragma unroll
        for (int i = 0; i < NT; i++) {         // B: BN*8 chunks
            const int c   = tid + i * 256;
            const int row = c >> 3;
            const int seg = c & 7;
            const int rb  = bn0 + row;
            const int ok  = (rb < N) ? 16 : 0;
            const float* gb = B + (size_t)(ok ? rb : 0) * K + k0 + seg * 4;
            const uint32_t db = sB + (row * GST + seg * 4) * 4;
            asm volatile("cp.async.cg.shared.global [%0], [%1], 16, %2;"
                         :: "r"(db), "l"(gb), "r"(ok));
        }
    };

    float acc[4][NT][4];
#pragma unroll
    for (int mt = 0; mt < 4; mt++)
#pragma unroll
        for (int nt = 0; nt < NT; nt++)
#pragma unroll
            for (int v = 0; v < 4; v++) acc[mt][nt][v] = 0.f;

    const int nk = K / GBK;
    load_tiles(0, 0);
    asm volatile("cp.async.commit_group;");

    for (int kt = 0; kt < nk; kt++) {
        const int cur = kt & 1;
        asm volatile("cp.async.wait_group 0;");
        __syncthreads();
        if (kt + 1 < nk) {
            load_tiles(cur ^ 1, (kt + 1) * GBK);
            asm volatile("cp.async.commit_group;");
        }
        const float* sa = Asm + cur * (GBM * GST);
        const float* sb = Bsm + cur * (BN * GST);

#pragma unroll
        for (int k8 = 0; k8 < GBK; k8 += 8) {
            uint32_t af[4][4], bf[NT][2];
#pragma unroll
            for (int mt = 0; mt < 4; mt++) {
                const int r = wm + mt * 16 + g;
                af[mt][0] = __float_as_uint(sa[r       * GST + k8 + tg]);
                af[mt][1] = __float_as_uint(sa[(r + 8) * GST + k8 + tg]);
                af[mt][2] = __float_as_uint(sa[r       * GST + k8 + tg + 4]);
                af[mt][3] = __float_as_uint(sa[(r + 8) * GST + k8 + tg + 4]);
            }
#pragma unroll
            for (int nt = 0; nt < NT; nt++) {
                const int rn = wn + nt * 8 + g;
                bf[nt][0] = __float_as_uint(sb[rn * GST + k8 + tg]);
                bf[nt][1] = __float_as_uint(sb[rn * GST + k8 + tg + 4]);
            }
#pragma unroll
            for (int mt = 0; mt < 4; mt++)
#pragma unroll
                for (int nt = 0; nt < NT; nt++)
                    MMA_TF32(acc[mt][nt][0], acc[mt][nt][1],
                             acc[mt][nt][2], acc[mt][nt][3],
                             af[mt][0], af[mt][1], af[mt][2], af[mt][3],
                             bf[nt][0], bf[nt][1]);
        }
        __syncthreads();
    }

#pragma unroll
    for (int mt = 0; mt < 4; mt++) {
        const int r0 = bm0 + wm + mt * 16 + g;
#pragma unroll
        for (int nt = 0; nt < NT; nt++) {
            const int cc = bn0 + wn + nt * 8 + tg * 2;
            if (cc < N) {
                *reinterpret_cast<float2*>(&C[(size_t)r0 * N + cc]) =
                    make_float2(acc[mt][nt][0], acc[mt][nt][1]);
                *reinterpret_cast<float2*>(&C[(size_t)(r0 + 8) * N + cc]) =
                    make_float2(acc[mt][nt][2], acc[mt][nt][3]);
            }
        }
    }
}

// ---------------------------------------------------------------------------
// RMSNorm — output rounded to tf32 (bitwise-identical to consumer-side cvt)
// ---------------------------------------------------------------------------
__global__ void __launch_bounds__(256) rmsnorm_kernel(
    const float* __restrict__ src, float* __restrict__ dst,
    const float* __restrict__ w, int R, int sstride, int dstride)
{
    const int row = blockIdx.x;
    const float* s = src + (size_t)row * sstride;
    float* d = dst + (size_t)row * dstride;

    float sum = 0.f;
    for (int i = threadIdx.x; i < R; i += 256) {
        float v = s[i];
        sum = fmaf(v, v, sum);
    }
    __shared__ float red[8];
#pragma unroll
    for (int o = 16; o; o >>= 1) sum += __shfl_down_sync(0xffffffffu, sum, o);
    if ((threadIdx.x & 31) == 0) red[threadIdx.x >> 5] = sum;
    __syncthreads();
    if (threadIdx.x < 8) {
        float v = red[threadIdx.x];
#pragma unroll
        for (int o = 4; o; o >>= 1) v += __shfl_down_sync(0xffu, v, o);
        if (threadIdx.x == 0) red[0] = v;
    }
    __syncthreads();
    const float mean = red[0] / (float)R;
    const float r = rsqrtf(mean + EPSF);
    for (int i = threadIdx.x; i < R; i += 256)
        d[i] = round_tf32(s[i] * r * w[i]);
}

// ---------------------------------------------------------------------------
// RoPE (unchanged)
// ---------------------------------------------------------------------------
__global__ void rope_tables_kernel()
{
    const int idx = blockIdx.x * blockDim.x + threadIdx.x;
    if (idx >= SEQ * (ROPE_D / 2)) return;
    const int t = idx / (ROPE_D / 2);
    const int i = idx % (ROPE_D / 2);
    const double freq = pow(500000.0, -(double)i / 32.0);
    const float ang = (float)t * (float)freq;
    g_cos[idx] = cosf(ang);
    g_sin[idx] = sinf(ang);
}

__global__ void rope_q_kernel()
{
    const int idx = blockIdx.x * blockDim.x + threadIdx.x;
    if (idx >= SEQ * NH * (ROPE_D / 2)) return;
    const int i  = idx & 31;
    const int th = idx >> 5;
    const int h  = th % NH;
    const int t  = th / NH;
    const float c = g_cos[t * 32 + i];
    const float s = g_sin[t * 32 + i];
    float* p = g_q + (size_t)t * (NH * QKD) + h * QKD + NOPE + 2 * i;
    const float e = p[0], o = p[1];
    p[0] = e * c - o * s;
    p[1] = o * c + e * s;
}

__global__ void rope_k_kernel()
{
    const int idx = blockIdx.x * blockDim.x + threadIdx.x;
    if (idx >= SEQ * (ROPE_D / 2)) return;
    const int i = idx & 31;
    const int t = idx >> 5;
    const float c = g_cos[t * 32 + i];
    const float s = g_sin[t * 32 + i];
    const float* src = g_kv + (size_t)t * (KVR + ROPE_D) + KVR + 2 * i;
    const float e = src[0], o = src[1];
    g_krope[t * ROPE_D + 2 * i]     = e * c - o * s;
    g_krope[t * ROPE_D + 2 * i + 1] = o * c + e * s;
}

// ---------------------------------------------------------------------------
// Tensor-core causal flash attention (R3 kernel; epilogue now tf32-rounds
// its output, matching what the w_o GEMM's cvt previously produced)
// ---------------------------------------------------------------------------
constexpr int QSTR = 200, VSTR = 72;
constexpr int ATT_SMEM_BYTES = (128 * QSTR + 64 * QSTR + 128 * VSTR) * 4;

__device__ __forceinline__ int kperm(int j) {
    return (j & 3) * 2 + (j >> 2);
}

__global__ void __launch_bounds__(256) attn_mma_kernel()
{
    extern __shared__ float sm[];
    float* Qs = sm;                     // [128][200]
    float* Ks = Qs + 128 * QSTR;        // [64][200]
    float* Vt = Ks + 64 * QSTR;         // [128][72]

    const int tid  = threadIdx.x;
    const int warp = tid >> 5;
    const int lane = tid & 31;
    const int g    = lane >> 2;
    const int tg   = lane & 3;
    const int bx   = blockIdx.x;
    const int qt   = (bx & 1) ? (15 - (bx >> 1)) : (bx >> 1);
    const int h    = blockIdx.y;
    const int qbase = qt * 128;
    const int r0   = warp * 16;
    const float scale = 0.07216878364870322f;  // 1/sqrt(192)

    for (int idx = tid; idx < 128 * 192; idx += 256) {
        const int r = idx / 192, d = idx % 192;
        const int pos = (d & ~7) + kperm(d & 7);
        Qs[r * QSTR + pos] =
            g_q[(size_t)(qbase + r) * (NH * QKD) + h * QKD + d] * scale;
    }

    float sacc[8][4];
    float oacc[16][4];
#pragma unroll
    for (int nv = 0; nv < 16; nv++)
#pragma unroll
        for (int v = 0; v < 4; v++) oacc[nv][v] = 0.f;
    float m0 = -INFINITY, m1 = -INFINITY, l0 = 0.f, l1 = 0.f;

    const int nkt = 2 * qt + 2;
    for (int kt = 0; kt < nkt; kt++) {
        const int kbase = kt * 64;
        __syncthreads();

        for (int idx = tid; idx < 64 * 192; idx += 256) {
            const int r = idx / 192, d = idx % 192;
            const int pos = (d & ~7) + kperm(d & 7);
            const float v = (d < NOPE)
                ? g_kvup[(size_t)(kbase + r) * (NH * KVUP_D) + h * KVUP_D + d]
                : g_krope[(size_t)(kbase + r) * ROPE_D + (d - NOPE)];
            Ks[r * QSTR + pos] = v;
        }
        for (int idx = tid; idx < 64 * 128; idx += 256) {
            const int r = idx >> 7, dv = idx & 127;
            const int pos = (r & ~7) + kperm(r & 7);
            Vt[dv * VSTR + pos] =
                g_kvup[(size_t)(kbase + r) * (NH * KVUP_D) + h * KVUP_D + NOPE + dv];
        }
        __syncthreads();

#pragma unroll
        for (int nf = 0; nf < 8; nf++)
#pragma unroll
            for (int v = 0; v < 4; v++) sacc[nf][v] = 0.f;

#pragma unroll
        for (int f = 0; f < 24; f++) {
            const float2 qa = *reinterpret_cast<const float2*>(
                &Qs[(r0 + g) * QSTR + f * 8 + tg * 2]);
            const float2 qb = *reinterpret_cast<const float2*>(
                &Qs[(r0 + g + 8) * QSTR + f * 8 + tg * 2]);
            const uint32_t a0 = f2tf32(qa.x), a1 = f2tf32(qb.x);
            const uint32_t a2 = f2tf32(qa.y), a3 = f2tf32(qb.y);
#pragma unroll
            for (int nf = 0; nf < 8; nf++) {
                const float2 kb = *reinterpret_cast<const float2*>(
                    &Ks[(nf * 8 + g) * QSTR + f * 8 + tg * 2]);
                MMA_TF32(sacc[nf][0], sacc[nf][1], sacc[nf][2], sacc[nf][3],
                         a0, a1, a2, a3, f2tf32(kb.x), f2tf32(kb.y));
            }
        }

        const int rg  = qbase + r0 + g;
        if (kbase + 63 > rg) {
#pragma unroll
            for (int nf = 0; nf < 8; nf++) {
                const int c0 = kbase + nf * 8 + tg * 2;
                if (c0     > rg)     sacc[nf][0] = -INFINITY;
                if (c0 + 1 > rg)     sacc[nf][1] = -INFINITY;
                if (c0     > rg + 8) sacc[nf][2] = -INFINITY;
                if (c0 + 1 > rg + 8) sacc[nf][3] = -INFINITY;
            }
        }

        float t0 = -INFINITY, t1 = -INFINITY;
#pragma unroll
        for (int nf = 0; nf < 8; nf++) {
            t0 = fmaxf(t0, fmaxf(sacc[nf][0], sacc[nf][1]));
            t1 = fmaxf(t1, fmaxf(sacc[nf][2], sacc[nf][3]));
        }
        t0 = fmaxf(t0, __shfl_xor_sync(0xffffffffu, t0, 1));
        t0 = fmaxf(t0, __shfl_xor_sync(0xffffffffu, t0, 2));
        t1 = fmaxf(t1, __shfl_xor_sync(0xffffffffu, t1, 1));
        t1 = fmaxf(t1, __shfl_xor_sync(0xffffffffu, t1, 2));
        const float nm0 = fmaxf(m0, t0), nm1 = fmaxf(m1, t1);
        const float al0 = __expf(m0 - nm0), al1 = __expf(m1 - nm1);
        m0 = nm0; m1 = nm1;

        float rs0 = 0.f, rs1 = 0.f;
#pragma unroll
        for (int nf = 0; nf < 8; nf++) {
            sacc[nf][0] = __expf(sacc[nf][0] - nm0);
            sacc[nf][1] = __expf(sacc[nf][1] - nm0);
            sacc[nf][2] = __expf(sacc[nf][2] - nm1);
            sacc[nf][3] = __expf(sacc[nf][3] - nm1);
            rs0 += sacc[nf][0] + sacc[nf][1];
            rs1 += sacc[nf][2] + sacc[nf][3];
        }
        rs0 += __shfl_xor_sync(0xffffffffu, rs0, 1);
        rs0 += __shfl_xor_sync(0xffffffffu, rs0, 2);
        rs1 += __shfl_xor_sync(0xffffffffu, rs1, 1);
        rs1 += __shfl_xor_sync(0xffffffffu, rs1, 2);
        l0 = l0 * al0 + rs0;
        l1 = l1 * al1 + rs1;

#pragma unroll
        for (int nv = 0; nv < 16; nv++) {
            oacc[nv][0] *= al0; oacc[nv][1] *= al0;
            oacc[nv][2] *= al1; oacc[nv][3] *= al1;
        }

        const int src0 = (lane & ~3) | (tg >> 1);
        const int src2 = src0 + 2;
        const bool odd = (tg & 1);
#pragma unroll
        for (int f2 = 0; f2 < 8; f2++) {
            const float x0 = __shfl_sync(0xffffffffu, sacc[f2][0], src0);
            const float x1 = __shfl_sync(0xffffffffu, sacc[f2][1], src0);
            const float x2 = __shfl_sync(0xffffffffu, sacc[f2][0], src2);
            const float x3 = __shfl_sync(0xffffffffu, sacc[f2][1], src2);
            const float y0 = __shfl_sync(0xffffffffu, sacc[f2][2], src0);
            const float y1 = __shfl_sync(0xffffffffu, sacc[f2][3], src0);
            const float y2 = __shfl_sync(0xffffffffu, sacc[f2][2], src2);
            const float y3 = __shfl_sync(0xffffffffu, sacc[f2][3], src2);
            const uint32_t a0 = f2tf32(odd ? x1 : x0);
            const uint32_t a1 = f2tf32(odd ? y1 : y0);
            const uint32_t a2 = f2tf32(odd ? x3 : x2);
            const uint32_t a3 = f2tf32(odd ? y3 : y2);
#pragma unroll
            for (int nv = 0; nv < 16; nv++) {
                const float2 vb = *reinterpret_cast<const float2*>(
                    &Vt[(nv * 8 + g) * VSTR + f2 * 8 + tg * 2]);
                MMA_TF32(oacc[nv][0], oacc[nv][1], oacc[nv][2], oacc[nv][3],
                         a0, a1, a2, a3, f2tf32(vb.x), f2tf32(vb.y));
            }
        }
    }

    const float inv0 = 1.f / l0, inv1 = 1.f / l1;
    const int rga = qbase + r0 + g;
#pragma unroll
    for (int nv = 0; nv < 16; nv++) {
        const int col = h * VDIM + nv * 8 + tg * 2;
        *reinterpret_cast<float2*>(&g_attn[(size_t)rga * (NH * VDIM) + col]) =
            make_float2(round_tf32(oacc[nv][0] * inv0),
                        round_tf32(oacc[nv][1] * inv0));
        *reinterpret_cast<float2*>(&g_attn[(size_t)(rga + 8) * (NH * VDIM) + col]) =
            make_float2(round_tf32(oacc[nv][2] * inv1),
                        round_tf32(oacc[nv][3] * inv1));
    }
}

// ---------------------------------------------------------------------------
// Launch
// ---------------------------------------------------------------------------
static inline void launch_gemm64(const float* A, const float* B, float* C,
                                 int M, int N, int K)
{
    dim3 grid((N + 63) / 64, M / GBM);
    gemm_tf32_kernel<64><<<grid, 256, gemm_smem_bytes<64>()>>>(A, B, C, M, N, K);
}
static inline void launch_gemm128(const float* A, const float* B, float* C,
                                  int M, int N, int K)
{
    dim3 grid((N + 127) / 128, M / GBM);
    gemm_tf32_kernel<128><<<grid, 256, gemm_smem_bytes<128>()>>>(A, B, C, M, N, K);
}
static inline void launch_round(const float* src, float* dst, int n)
{
    const int n4 = n / 4;
    int grid = (n4 + 1023) / 1024;
    if (grid > 592) grid = 592;
    round_tf32_kernel<<<grid, 256>>>((const float4*)src, (float4*)dst, n4);
}

extern "C" void kernel_launch(void* const* d_in, const int* in_sizes, int n_in,
                              void* d_out, int out_size)
{
    const float* x         = (const float*)d_in[0];
    const float* w_q_down  = (const float*)d_in[1];
    const float* q_norm_w  = (const float*)d_in[2];
    const float* w_q_up    = (const float*)d_in[3];
    const float* w_kv_down = (const float*)d_in[4];
    const float* kv_norm_w = (const float*)d_in[5];
    const float* w_kv_up   = (const float*)d_in[6];
    const float* w_o       = (const float*)d_in[7];
    float* out = (float*)d_out;

    float *cq, *q, *kv, *ckv, *kvup, *attn;
    float *xr, *wqd, *wqu, *wkvd, *wkvu, *wo;
    cudaGetSymbolAddress((void**)&cq,   g_cq);
    cudaGetSymbolAddress((void**)&q,    g_q);
    cudaGetSymbolAddress((void**)&kv,   g_kv);
    cudaGetSymbolAddress((void**)&ckv,  g_ckv);
    cudaGetSymbolAddress((void**)&kvup, g_kvup);
    cudaGetSymbolAddress((void**)&attn, g_attn);
    cudaGetSymbolAddress((void**)&xr,   g_x);
    cudaGetSymbolAddress((void**)&wqd,  g_wqd);
    cudaGetSymbolAddress((void**)&wqu,  g_wqu);
    cudaGetSymbolAddress((void**)&wkvd, g_wkvd);
    cudaGetSymbolAddress((void**)&wkvu, g_wkvu);
    cudaGetSymbolAddress((void**)&wo,   g_wo);

    cudaFuncSetAttribute(attn_mma_kernel,
                         cudaFuncAttributeMaxDynamicSharedMemorySize,
                         ATT_SMEM_BYTES);
    cudaFuncSetAttribute(gemm_tf32_kernel<64>,
                         cudaFuncAttributeMaxDynamicSharedMemorySize,
                         gemm_smem_bytes<64>());
    cudaFuncSetAttribute(gemm_tf32_kernel<128>,
                         cudaFuncAttributeMaxDynamicSharedMemorySize,
                         gemm_smem_bytes<128>());

    // 0. tf32 pre-rounding of x and all weights
    launch_round(x,         xr,   SEQ * DIM);
    launch_round(w_q_down,  wqd,  QR * DIM);
    launch_round(w_q_up,    wqu,  NH * QKD * QR);
    launch_round(w_kv_down, wkvd, (KVR + ROPE_D) * DIM);
    launch_round(w_kv_up,   wkvu, NH * KVUP_D * KVR);
    launch_round(w_o,       wo,   DIM * NH * VDIM);

    // 1. c_q_pre = x @ w_q_down.T               [2048, 1536]
    launch_gemm64(xr, wqd, cq, SEQ, QR, DIM);
    // 2. c_q = rmsnorm(c_q_pre), tf32-rounded (in place)
    rmsnorm_kernel<<<SEQ, 256>>>(cq, cq, q_norm_w, QR, QR, QR);
    // 3. q = c_q @ w_q_up.T                     [2048, 3072]
    launch_gemm128(cq, wqu, q, SEQ, NH * QKD, QR);
    // 4. kv = x @ w_kv_down.T                   [2048, 576]
    launch_gemm64(xr, wkvd, kv, SEQ, KVR + ROPE_D, DIM);
    // 5. c_kv = rmsnorm(kv[:, :512]), tf32-rounded
    rmsnorm_kernel<<<SEQ, 256>>>(kv, ckv, kv_norm_w, KVR, KVR + ROPE_D, KVR);
    // 6. RoPE tables
    rope_tables_kernel<<<(SEQ * 32 + 255) / 256, 256>>>();
    // 7. RoPE on q (in place) and k_rope
    rope_q_kernel<<<(SEQ * NH * 32 + 255) / 256, 256>>>();
    rope_k_kernel<<<(SEQ * 32 + 255) / 256, 256>>>();
    // 8. kv_up = c_kv @ w_kv_up.T               [2048, 4096]
    launch_gemm128(ckv, wkvu, kvup, SEQ, NH * KVUP_D, KVR);
    // 9. tensor-core causal attention -> g_attn [2048, 2048] (tf32-rounded)
    attn_mma_kernel<<<dim3(SEQ / 128, NH), 256, ATT_SMEM_BYTES>>>();
    // 10. out = attn @ w_o.T                    [2048, 2048]
    launch_gemm64(attn, wo, out, SEQ, DIM, NH * VDIM);
}